// round 5
// baseline (speedup 1.0000x reference)
#include <cuda_runtime.h>
#include <cstddef>

#define BATCH 4
#define HW 16384   // 128*128

// ---------------- scratch (device globals; no allocation allowed) ----------------
__device__ float g_q   [(size_t)BATCH*256*HW];   // 64MB  q = relu(Wkq@feats+b)
__device__ float g_v   [(size_t)BATCH*256*HW];   // 64MB  v = Wv@feats+b
__device__ float g_ctx [(size_t)BATCH*256*HW];   // 64MB  attention output (chan-major)
__device__ float g_key [(size_t)BATCH*256*112];  // pooled q, padded S->112 (pads stay 0)
__device__ float g_valt[(size_t)BATCH*112*256];  // pooled v, transposed [s][c], pads 0
__device__ float g_weff[512*256];
__device__ float g_beff[512];

// ---------------- W_eff = W_bot[:, :512] @ W_out ; b_eff = W_bot[:,:512]@b_out + b_bot
__global__ void weff_kernel(const float* __restrict__ w_out, const float* __restrict__ b_out,
                            const float* __restrict__ w_bot, const float* __restrict__ b_bot)
{
    int m = blockIdx.x;      // 0..511
    int k = threadIdx.x;     // 0..255
    float a0 = 0.f, a1 = 0.f, a2 = 0.f, a3 = 0.f;
    for (int j = 0; j < 512; j += 4) {
        a0 += w_bot[m*1024 + j + 0] * w_out[(j + 0)*256 + k];
        a1 += w_bot[m*1024 + j + 1] * w_out[(j + 1)*256 + k];
        a2 += w_bot[m*1024 + j + 2] * w_out[(j + 2)*256 + k];
        a3 += w_bot[m*1024 + j + 3] * w_out[(j + 3)*256 + k];
    }
    g_weff[m*256 + k] = (a0 + a1) + (a2 + a3);
    if (k == 0) {
        float bb = b_bot[m];
        for (int j = 0; j < 512; j++) bb += w_bot[m*1024 + j] * b_out[j];
        g_beff[m] = bb;
    }
}

// ---------------- tiled fp32 GEMM, 128x128 block, 8x8 per thread, BK=16 -----------
// MODE 0: out rows 0..255 -> q (bias b_kq, relu), rows 256..511 -> v (bias b_v). K=512, B=feats.
// MODE 1: final out = relu(Weff@ctx + Wbot_right@feats + beff).          K=768.
template<int MODE>
__global__ __launch_bounds__(256, 2)
void gemm_kernel(const float* __restrict__ feats,
                 const float* __restrict__ w_kq, const float* __restrict__ b_kq,
                 const float* __restrict__ w_v,  const float* __restrict__ b_v,
                 const float* __restrict__ w_bot,
                 float* __restrict__ out)
{
    constexpr int K = (MODE == 0) ? 512 : 768;
    __shared__ float As[16*132];
    __shared__ float Bs[16*128];

    const int tid = threadIdx.x;
    const int n0  = blockIdx.x * 128;
    const int m0  = blockIdx.y * 128;
    const int b   = blockIdx.z;
    const int tx4 = (tid & 15) * 4;
    const int ty4 = (tid >> 4) * 4;

    float acc[8][8];
#pragma unroll
    for (int i = 0; i < 8; i++)
#pragma unroll
        for (int j = 0; j < 8; j++) acc[i][j] = 0.f;

    const int ar = tid >> 2;          // 0..63
    const int ac = (tid & 3) * 4;     // 0,4,8,12

    for (int k0 = 0; k0 < K; k0 += 16) {
        // A tile [128 m x 16 k] -> As[k][m] (transposed)
#pragma unroll
        for (int u = 0; u < 2; u++) {
            int m = m0 + ar + 64*u;
            int k = k0 + ac;
            const float* src;
            if (MODE == 0)
                src = (m < 256) ? (w_kq + (size_t)m*512 + k) : (w_v + (size_t)(m-256)*512 + k);
            else
                src = (k < 256) ? (g_weff + (size_t)m*256 + k) : (w_bot + (size_t)m*1024 + 256 + k);
            float4 av = *(const float4*)src;
            As[(ac+0)*132 + ar + 64*u] = av.x;
            As[(ac+1)*132 + ar + 64*u] = av.y;
            As[(ac+2)*132 + ar + 64*u] = av.z;
            As[(ac+3)*132 + ar + 64*u] = av.w;
        }
        // B tile [16 k x 128 n]
#pragma unroll
        for (int u = 0; u < 2; u++) {
            int e4 = tid + 256*u;           // 0..511 float4 slots
            int r  = e4 >> 5;               // 0..15
            int c  = (e4 & 31) * 4;         // 0..124
            int k  = k0 + r;
            const float* src;
            if (MODE == 0)
                src = feats + ((size_t)b*512 + k)*HW + n0 + c;
            else
                src = (k < 256) ? (g_ctx + ((size_t)b*256 + k)*HW + n0 + c)
                                : (feats + ((size_t)b*512 + (k-256))*HW + n0 + c);
            *(float4*)&Bs[r*128 + c] = *(const float4*)src;
        }
        __syncthreads();
#pragma unroll
        for (int kk = 0; kk < 16; kk++) {
            float a[8], bb[8];
            *(float4*)&a[0]  = *(float4*)&As[kk*132 + ty4];
            *(float4*)&a[4]  = *(float4*)&As[kk*132 + 64 + ty4];
            *(float4*)&bb[0] = *(float4*)&Bs[kk*128 + tx4];
            *(float4*)&bb[4] = *(float4*)&Bs[kk*128 + 64 + tx4];
#pragma unroll
            for (int i = 0; i < 8; i++)
#pragma unroll
                for (int j = 0; j < 8; j++)
                    acc[i][j] += a[i] * bb[j];
        }
        __syncthreads();
    }

    // epilogue
#pragma unroll
    for (int i = 0; i < 8; i++) {
        int m = m0 + ty4 + ((i < 4) ? i : (64 + i - 4));
        float bias; float* dst; bool do_relu;
        if (MODE == 0) {
            bool isq = (m < 256);
            bias    = isq ? b_kq[m] : b_v[m - 256];
            dst     = isq ? (g_q + ((size_t)b*256 + m)*HW) : (g_v + ((size_t)b*256 + (m-256))*HW);
            do_relu = isq;
        } else {
            bias    = g_beff[m];
            dst     = out + ((size_t)b*512 + m)*HW;
            do_relu = true;
        }
        float4 o0, o1;
        o0.x = acc[i][0]+bias; o0.y = acc[i][1]+bias; o0.z = acc[i][2]+bias; o0.w = acc[i][3]+bias;
        o1.x = acc[i][4]+bias; o1.y = acc[i][5]+bias; o1.z = acc[i][6]+bias; o1.w = acc[i][7]+bias;
        if (do_relu) {
            o0.x = fmaxf(o0.x,0.f); o0.y = fmaxf(o0.y,0.f); o0.z = fmaxf(o0.z,0.f); o0.w = fmaxf(o0.w,0.f);
            o1.x = fmaxf(o1.x,0.f); o1.y = fmaxf(o1.y,0.f); o1.z = fmaxf(o1.z,0.f); o1.w = fmaxf(o1.w,0.f);
        }
        *(float4*)&dst[n0 + tx4]      = o0;
        *(float4*)&dst[n0 + 64 + tx4] = o1;
    }
}

// ---------------- adaptive pooling via per-channel integral image -----------------
// grid: (2 which, 256 chan, 4 batch), 128 threads, dyn smem 128*129*4 = 66048 B
__global__ void pool_kernel()
{
    extern __shared__ float P[];   // [128][129]
    const int b = blockIdx.z, c = blockIdx.y, which = blockIdx.x;
    const int t = threadIdx.x;     // 0..127
    const float* src = (which == 0 ? g_q : g_v) + ((size_t)b*256 + c)*HW;

    for (int i = 0; i < 128; i++) P[i*129 + t] = src[i*128 + t];
    __syncthreads();
    { // row prefix (thread = row)
        float s = 0.f;
        for (int j = 0; j < 128; j++) { s += P[t*129 + j]; P[t*129 + j] = s; }
    }
    __syncthreads();
    { // column prefix (thread = col)
        float s = 0.f;
        for (int i = 0; i < 128; i++) { s += P[i*129 + t]; P[i*129 + t] = s; }
    }
    __syncthreads();
    if (t < 110) {
        int sidx = t, sc, idx;
        if      (sidx == 0) { sc = 1; idx = 0; }
        else if (sidx < 10) { sc = 3; idx = sidx - 1; }
        else if (sidx < 46) { sc = 6; idx = sidx - 10; }
        else                { sc = 8; idx = sidx - 46; }
        int i = idx / sc, j = idx % sc;
        int h0 = (i*128)/sc, h1 = ((i+1)*128 + sc - 1)/sc;
        int w0 = (j*128)/sc, w1 = ((j+1)*128 + sc - 1)/sc;
        float s11 =                      P[(h1-1)*129 + (w1-1)];
        float s01 = (h0 > 0)           ? P[(h0-1)*129 + (w1-1)] : 0.f;
        float s10 = (w0 > 0)           ? P[(h1-1)*129 + (w0-1)] : 0.f;
        float s00 = (h0 > 0 && w0 > 0) ? P[(h0-1)*129 + (w0-1)] : 0.f;
        float avg = (s11 - s01 - s10 + s00) / (float)((h1 - h0)*(w1 - w0));
        if (which == 0) g_key [((size_t)b*256 + c)*112 + sidx] = avg;
        else            g_valt[((size_t)b*112 + sidx)*256 + c] = avg;
    }
}

// ---------------- fused attention: sim GEMM -> softmax -> ctx GEMM ----------------
// grid: (128 pixel-tiles, 4 batch), 256 threads
// dyn smem: sim 128*113 + valt 112*256 + qs 8*132 + ks 8*128 = 45216 floats = 180864 B
__global__ __launch_bounds__(256, 1)
void attn_kernel()
{
    extern __shared__ float sm[];
    float* sim  = sm;                   // [128][113]
    float* valt = sm + 128*113;         // [112][256]
    float* qs   = valt + 112*256;       // [8][132]
    float* ks   = qs + 8*132;           // [8][128]

    const int b   = blockIdx.y;
    const int n0  = blockIdx.x * 128;
    const int tid = threadIdx.x;
    const int tx  = tid & 15, ty = tid >> 4;

    const float* gvt = g_valt + (size_t)b*112*256;
    for (int i = tid; i < 112*256; i += 256) valt[i] = gvt[i];

    float acc[8][8];
#pragma unroll
    for (int i = 0; i < 8; i++)
#pragma unroll
        for (int j = 0; j < 8; j++) acc[i][j] = 0.f;

    const float* gq0 = g_q   + ((size_t)b*256)*HW + n0;
    const float* gk0 = g_key + (size_t)b*256*112;

    for (int k0 = 0; k0 < 256; k0 += 8) {
        __syncthreads();
#pragma unroll
        for (int i = 0; i < 4; i++) {
            int e = tid + 256*i; int r = e >> 7, cc = e & 127;
            qs[r*132 + cc] = gq0[(size_t)(k0 + r)*HW + cc];
        }
#pragma unroll
        for (int i = 0; i < 4; i++) {
            int e = tid + 256*i; int r = e >> 7, cc = e & 127;
            ks[r*128 + cc] = (cc < 112) ? gk0[(k0 + r)*112 + cc] : 0.f;
        }
        __syncthreads();
#pragma unroll
        for (int kk = 0; kk < 8; kk++) {
            float av[8], bv[8];
#pragma unroll
            for (int i = 0; i < 8; i++) av[i] = qs[kk*132 + tx + 16*i];
#pragma unroll
            for (int j = 0; j < 8; j++) bv[j] = ks[kk*128 + ty + 14*j];
#pragma unroll
            for (int i = 0; i < 8; i++)
#pragma unroll
                for (int j = 0; j < 8; j++)
                    acc[i][j] += av[i] * bv[j];
        }
    }
    __syncthreads();
    if (ty < 14) {
#pragma unroll
        for (int i = 0; i < 8; i++)
#pragma unroll
            for (int j = 0; j < 8; j++)
                sim[(tx + 16*i)*113 + ty + 14*j] = acc[i][j] * 0.0625f;  // * Ck^-0.5
    }
    __syncthreads();
    if (tid < 128) {
        float* row = sim + tid*113;
        float mx = -1e30f;
        for (int s = 0; s < 110; s++) mx = fmaxf(mx, row[s]);
        float sum = 0.f;
        for (int s = 0; s < 110; s++) { float e = __expf(row[s] - mx); row[s] = e; sum += e; }
        float inv = 1.f / sum;
        for (int s = 0; s < 110; s++) row[s] *= inv;
        row[110] = 0.f; row[111] = 0.f;
    }
    __syncthreads();

    float* gctx = g_ctx + (size_t)b*256*HW + n0;
#pragma unroll
    for (int h = 0; h < 2; h++) {
#pragma unroll
        for (int i = 0; i < 8; i++)
#pragma unroll
            for (int j = 0; j < 8; j++) acc[i][j] = 0.f;
#pragma unroll 4
        for (int k = 0; k < 112; k++) {
            float av[8], bv[8];
#pragma unroll
            for (int i = 0; i < 8; i++) av[i] = sim[(tx + 16*i)*113 + k];
#pragma unroll
            for (int j = 0; j < 8; j++) bv[j] = valt[k*256 + ty + 16*j + 128*h];
#pragma unroll
            for (int i = 0; i < 8; i++)
#pragma unroll
                for (int j = 0; j < 8; j++)
                    acc[i][j] += av[i] * bv[j];
        }
#pragma unroll
        for (int j = 0; j < 8; j++) {
            int c = ty + 16*j + 128*h;
#pragma unroll
            for (int i = 0; i < 8; i++)
                gctx[(size_t)c*HW + tx + 16*i] = acc[i][j];
        }
    }
}

// ----------------------------------------------------------------------------------
extern "C" void kernel_launch(void* const* d_in, const int* in_sizes, int n_in,
                              void* d_out, int out_size)
{
    const float* feats = (const float*)d_in[0];
    const float* w_kq  = (const float*)d_in[1];
    const float* b_kq  = (const float*)d_in[2];
    const float* w_v   = (const float*)d_in[3];
    const float* b_v   = (const float*)d_in[4];
    const float* w_out = (const float*)d_in[5];
    const float* b_out = (const float*)d_in[6];
    const float* w_bot = (const float*)d_in[7];
    const float* b_bot = (const float*)d_in[8];
    float* out = (float*)d_out;

    const int pool_smem = 128*129*4;                       // 66048
    const int attn_smem = (128*113 + 112*256 + 8*132 + 8*128) * 4;  // 180864
    cudaFuncSetAttribute(pool_kernel, cudaFuncAttributeMaxDynamicSharedMemorySize, pool_smem);
    cudaFuncSetAttribute(attn_kernel, cudaFuncAttributeMaxDynamicSharedMemorySize, attn_smem);

    weff_kernel<<<512, 256>>>(w_out, b_out, w_bot, b_bot);
    gemm_kernel<0><<<dim3(128, 4, BATCH), 256>>>(feats, w_kq, b_kq, w_v, b_v, w_bot, out);
    pool_kernel<<<dim3(2, 256, BATCH), 128, pool_smem>>>();
    attn_kernel<<<dim3(128, BATCH), 256, attn_smem>>>();
    gemm_kernel<1><<<dim3(128, 4, BATCH), 256>>>(feats, w_kq, b_kq, w_v, b_v, w_bot, out);
}

// round 8
// speedup vs baseline: 1.3902x; 1.3902x over previous
#include <cuda_runtime.h>
#include <cuda_bf16.h>
#include <cstddef>
#include <cstdint>

#define BATCH 4
#define HW 16384   // 128*128

// ---------------- scratch (device globals; no allocation allowed) ----------------
__device__ float g_q   [(size_t)BATCH*256*HW];   // 64MB  q = relu(Wkq@feats+b)
__device__ float g_v   [(size_t)BATCH*256*HW];   // 64MB  v = Wv@feats+b
__device__ float g_ctx [(size_t)BATCH*256*HW];   // 64MB  attention output (chan-major)
__device__ float g_key [(size_t)BATCH*256*112];  // pooled q, padded S->112 (pads stay 0)
__device__ float g_valt[(size_t)BATCH*112*256];  // pooled v, transposed [s][c], pads 0
__device__ float g_weff[512*256];
__device__ float g_beff[512];

// ============================ helpers ===============================
__device__ __forceinline__ uint32_t smem_u32(const void* p) {
    uint32_t a;
    asm("{ .reg .u64 t; cvta.to.shared.u64 t, %1; cvt.u32.u64 %0, t; }" : "=r"(a) : "l"(p));
    return a;
}
__device__ __forceinline__ uint32_t swz(uint32_t o) { return o ^ ((o >> 3) & 0x70); }

__device__ __forceinline__ void ldsm4(uint32_t* r, uint32_t addr) {
    asm volatile("ldmatrix.sync.aligned.m8n8.x4.shared.b16 {%0,%1,%2,%3}, [%4];"
                 : "=r"(r[0]), "=r"(r[1]), "=r"(r[2]), "=r"(r[3]) : "r"(addr));
}
__device__ __forceinline__ void ldsm4t(uint32_t* r, uint32_t addr) {
    asm volatile("ldmatrix.sync.aligned.m8n8.x4.trans.shared.b16 {%0,%1,%2,%3}, [%4];"
                 : "=r"(r[0]), "=r"(r[1]), "=r"(r[2]), "=r"(r[3]) : "r"(addr));
}
__device__ __forceinline__ void mma16816(float* c, const uint32_t* a, uint32_t b0, uint32_t b1) {
    asm volatile(
        "mma.sync.aligned.m16n8k16.row.col.f32.bf16.bf16.f32 "
        "{%0,%1,%2,%3}, {%4,%5,%6,%7}, {%8,%9}, {%0,%1,%2,%3};"
        : "+f"(c[0]), "+f"(c[1]), "+f"(c[2]), "+f"(c[3])
        : "r"(a[0]), "r"(a[1]), "r"(a[2]), "r"(a[3]), "r"(b0), "r"(b1));
}
__device__ __forceinline__ void bf16split(float x, unsigned short& h, unsigned short& l) {
    __nv_bfloat16 hb = __float2bfloat16_rn(x);
    float r = x - __bfloat162float(hb);
    __nv_bfloat16 lb = __float2bfloat16_rn(r);
    h = __bfloat16_as_ushort(hb);
    l = __bfloat16_as_ushort(lb);
}

// ---------------- W_eff = W_bot[:, :512] @ W_out ; b_eff = W_bot[:,:512]@b_out + b_bot
__global__ void weff_kernel(const float* __restrict__ w_out, const float* __restrict__ b_out,
                            const float* __restrict__ w_bot, const float* __restrict__ b_bot)
{
    int m = blockIdx.x;      // 0..511
    int k = threadIdx.x;     // 0..255
    float a0 = 0.f, a1 = 0.f, a2 = 0.f, a3 = 0.f;
    for (int j = 0; j < 512; j += 4) {
        a0 += w_bot[m*1024 + j + 0] * w_out[(j + 0)*256 + k];
        a1 += w_bot[m*1024 + j + 1] * w_out[(j + 1)*256 + k];
        a2 += w_bot[m*1024 + j + 2] * w_out[(j + 2)*256 + k];
        a3 += w_bot[m*1024 + j + 3] * w_out[(j + 3)*256 + k];
    }
    g_weff[m*256 + k] = (a0 + a1) + (a2 + a3);
    if (k == 0) {
        float bb = b_bot[m];
        for (int j = 0; j < 512; j++) bb += w_bot[m*1024 + j] * b_out[j];
        g_beff[m] = bb;
    }
}

// ================= mma.sync bf16 3-split GEMM (fp32-accurate) =====================
// 128x128 tile, 8 warps (each 64m x 32n), BK=64, double-buffered smem.
// A: [m][k] bf16 hi/lo, SW128 swizzle (128B rows). B: [k][n] bf16 hi/lo, 272B rows,
// loaded with ldmatrix.trans. acc += Ahi*Bhi + Ahi*Blo + Alo*Bhi (fp32 accum).
// MODE 0: A = [w_kq; w_v] (512x512), B = feats. out rows<256 -> q (relu), else v.
// MODE 1: A = [Weff | Wbot_right] (512x768), B = [ctx; feats]. out = relu(+beff).
#define A_BYTES 16384          // 128*128
#define B_BYTES 17408          // 64*272
#define STAGE   67584          // 2*A + 2*B  (also = 128*132*4 epilogue staging)

template<int MODE>
__global__ __launch_bounds__(256)
void mma_gemm_kernel(const float* __restrict__ feats,
                     const float* __restrict__ w_kq, const float* __restrict__ b_kq,
                     const float* __restrict__ w_v,  const float* __restrict__ b_v,
                     const float* __restrict__ w_bot,
                     float* __restrict__ out)
{
    constexpr int K  = (MODE == 0) ? 512 : 768;
    constexpr int NC = K / 64;
    extern __shared__ char dyn[];
    char* base = (char*)(((uintptr_t)dyn + 1023) & ~(uintptr_t)1023);

    const int tid  = threadIdx.x;
    const int wid  = tid >> 5, lane = tid & 31;
    const int wm   = wid & 1,  wn   = wid >> 1;
    const int n0   = blockIdx.x * 128;
    const int m0   = blockIdx.y * 128;
    const int b    = blockIdx.z;
    const int lr   = lane & 15, lh = lane >> 4;

    float acc[4][4][4];
#pragma unroll
    for (int i = 0; i < 4; i++)
#pragma unroll
        for (int j = 0; j < 4; j++)
#pragma unroll
            for (int r = 0; r < 4; r++) acc[i][j][r] = 0.f;

    // ---- chunk loader: gmem fp32 -> bf16 hi/lo smem ----
    auto load_chunk = [&](int c) {
        char* sAh = base + (c & 1) * STAGE;
        char* sAl = sAh + A_BYTES;
        char* sBh = sAl + A_BYTES;
        char* sBl = sBh + B_BYTES;
        const int k0 = c * 64;
        // A: [128m x 64k], float4 along k
#pragma unroll
        for (int u = 0; u < 8; u++) {
            int idx4 = tid + 256 * u;
            int m = idx4 >> 4, kq = idx4 & 15, k = kq * 4;
            int mg = m0 + m;
            const float* src;
            if (MODE == 0)
                src = ((mg < 256) ? (w_kq + (size_t)mg*512) : (w_v + (size_t)(mg-256)*512)) + k0 + k;
            else {
                int kg = k0 + k;
                src = (kg < 256) ? (g_weff + (size_t)mg*256 + kg)
                                 : (w_bot + (size_t)mg*1024 + 256 + kg);
            }
            float4 v4 = *(const float4*)src;
            unsigned short h0,h1,h2,h3,l0,l1,l2,l3;
            bf16split(v4.x,h0,l0); bf16split(v4.y,h1,l1);
            bf16split(v4.z,h2,l2); bf16split(v4.w,h3,l3);
            uint32_t off = swz((uint32_t)(m*128 + k*2));
            *(uint2*)(sAh + off) = make_uint2((uint32_t)h0 | ((uint32_t)h1<<16),
                                              (uint32_t)h2 | ((uint32_t)h3<<16));
            *(uint2*)(sAl + off) = make_uint2((uint32_t)l0 | ((uint32_t)l1<<16),
                                              (uint32_t)l2 | ((uint32_t)l3<<16));
        }
        // B: [64k x 128n] kept K-major, float4 along n (coalesced)
#pragma unroll
        for (int u = 0; u < 8; u++) {
            int idx4 = tid + 256 * u;
            int k = idx4 >> 5, nq = idx4 & 31, n = nq * 4;
            const float* src;
            if (MODE == 0)
                src = feats + ((size_t)b*512 + k0 + k) * HW + n0 + n;
            else {
                int kg = k0 + k;
                src = (kg < 256) ? (g_ctx + ((size_t)b*256 + kg) * HW + n0 + n)
                                 : (feats + ((size_t)b*512 + (kg-256)) * HW + n0 + n);
            }
            float4 v4 = *(const float4*)src;
            unsigned short h0,h1,h2,h3,l0,l1,l2,l3;
            bf16split(v4.x,h0,l0); bf16split(v4.y,h1,l1);
            bf16split(v4.z,h2,l2); bf16split(v4.w,h3,l3);
            uint32_t off = (uint32_t)(k*272 + n*2);
            *(uint2*)(sBh + off) = make_uint2((uint32_t)h0 | ((uint32_t)h1<<16),
                                              (uint32_t)h2 | ((uint32_t)h3<<16));
            *(uint2*)(sBl + off) = make_uint2((uint32_t)l0 | ((uint32_t)l1<<16),
                                              (uint32_t)l2 | ((uint32_t)l3<<16));
        }
    };

    // ---- compute on a resident chunk ----
    auto compute = [&](int c) {
        char* sAh = base + (c & 1) * STAGE;
        uint32_t aH = smem_u32(sAh);
        uint32_t aL = aH + A_BYTES;
        uint32_t bH = aL + A_BYTES;
        uint32_t bL = bH + B_BYTES;
#pragma unroll
        for (int kk = 0; kk < 4; kk++) {
            const int k0 = kk * 16;
            uint32_t ah[4][4], al[4][4];
#pragma unroll
            for (int mi = 0; mi < 4; mi++) {
                int row = wm*64 + mi*16 + lr;
                uint32_t off = swz((uint32_t)(row*128 + (k0 + lh*8)*2));
                ldsm4(ah[mi], aH + off);
                ldsm4(al[mi], aL + off);
            }
            uint32_t bh[2][4], bl[2][4];
#pragma unroll
            for (int p = 0; p < 2; p++) {
                int brow = k0 + lr;                    // k row
                int bcol = wn*32 + p*16 + lh*8;        // n col
                uint32_t off = (uint32_t)(brow*272 + bcol*2);
                ldsm4t(bh[p], bH + off);
                ldsm4t(bl[p], bL + off);
            }
#pragma unroll
            for (int mi = 0; mi < 4; mi++)
#pragma unroll
                for (int nj = 0; nj < 4; nj++) {
                    int p = nj >> 1, q = (nj & 1) * 2;
                    mma16816(acc[mi][nj], ah[mi], bh[p][q], bh[p][q+1]);
                    mma16816(acc[mi][nj], ah[mi], bl[p][q], bl[p][q+1]);
                    mma16816(acc[mi][nj], al[mi], bh[p][q], bh[p][q+1]);
                }
        }
    };

    load_chunk(0);
    __syncthreads();
    for (int c = 0; c < NC; c++) {
        if (c + 1 < NC) load_chunk(c + 1);
        compute(c);
        __syncthreads();
    }

    // ---- epilogue: frags -> smem [128][132] -> coalesced gmem + bias/relu ----
    float* sD = (float*)base;
    {
        int tq = lane & 3, tr = lane >> 2;
#pragma unroll
        for (int mi = 0; mi < 4; mi++)
#pragma unroll
            for (int nj = 0; nj < 4; nj++) {
                int r0 = wm*64 + mi*16 + tr;
                int cc = wn*32 + nj*8 + tq*2;
                *(float2*)&sD[(size_t)r0*132 + cc]       = make_float2(acc[mi][nj][0], acc[mi][nj][1]);
                *(float2*)&sD[(size_t)(r0+8)*132 + cc]   = make_float2(acc[mi][nj][2], acc[mi][nj][3]);
            }
    }
    __syncthreads();
#pragma unroll
    for (int u = 0; u < 16; u++) {
        int idx4 = tid + 256 * u;            // 0..4095
        int m = idx4 >> 5;                   // 0..127
        int n = (idx4 & 31) * 4;
        int mg = m0 + m;
        float bias; float* dst; bool rl;
        if (MODE == 0) {
            bool isq = (mg < 256);
            bias = isq ? b_kq[mg] : b_v[mg - 256];
            dst  = isq ? (g_q + ((size_t)b*256 + mg) * HW)
                       : (g_v + ((size_t)b*256 + (mg-256)) * HW);
            rl = isq;
        } else {
            bias = g_beff[mg];
            dst  = out + ((size_t)b*512 + mg) * HW;
            rl = true;
        }
        float4 o;
        o.x = sD[(size_t)m*132 + n + 0] + bias;
        o.y = sD[(size_t)m*132 + n + 1] + bias;
        o.z = sD[(size_t)m*132 + n + 2] + bias;
        o.w = sD[(size_t)m*132 + n + 3] + bias;
        if (rl) {
            o.x = fmaxf(o.x, 0.f); o.y = fmaxf(o.y, 0.f);
            o.z = fmaxf(o.z, 0.f); o.w = fmaxf(o.w, 0.f);
        }
        *(float4*)(dst + n0 + n) = o;
    }
}

// ---------------- adaptive pooling via per-channel integral image -----------------
__global__ void pool_kernel()
{
    extern __shared__ float P[];   // [128][129]
    const int b = blockIdx.z, c = blockIdx.y, which = blockIdx.x;
    const int t = threadIdx.x;     // 0..127
    const float* src = (which == 0 ? g_q : g_v) + ((size_t)b*256 + c)*HW;

    for (int i = 0; i < 128; i++) P[i*129 + t] = src[i*128 + t];
    __syncthreads();
    { float s = 0.f;
      for (int j = 0; j < 128; j++) { s += P[t*129 + j]; P[t*129 + j] = s; } }
    __syncthreads();
    { float s = 0.f;
      for (int i = 0; i < 128; i++) { s += P[i*129 + t]; P[i*129 + t] = s; } }
    __syncthreads();
    if (t < 110) {
        int sidx = t, sc, idx;
        if      (sidx == 0) { sc = 1; idx = 0; }
        else if (sidx < 10) { sc = 3; idx = sidx - 1; }
        else if (sidx < 46) { sc = 6; idx = sidx - 10; }
        else                { sc = 8; idx = sidx - 46; }
        int i = idx / sc, j = idx % sc;
        int h0 = (i*128)/sc, h1 = ((i+1)*128 + sc - 1)/sc;
        int w0 = (j*128)/sc, w1 = ((j+1)*128 + sc - 1)/sc;
        float s11 =                      P[(h1-1)*129 + (w1-1)];
        float s01 = (h0 > 0)           ? P[(h0-1)*129 + (w1-1)] : 0.f;
        float s10 = (w0 > 0)           ? P[(h1-1)*129 + (w0-1)] : 0.f;
        float s00 = (h0 > 0 && w0 > 0) ? P[(h0-1)*129 + (w0-1)] : 0.f;
        float avg = (s11 - s01 - s10 + s00) / (float)((h1 - h0)*(w1 - w0));
        if (which == 0) g_key [((size_t)b*256 + c)*112 + sidx] = avg;
        else            g_valt[((size_t)b*112 + sidx)*256 + c] = avg;
    }
}

// ---------------- fused attention: sim GEMM -> softmax -> ctx GEMM ----------------
__global__ __launch_bounds__(256, 1)
void attn_kernel()
{
    extern __shared__ float sm[];
    float* sim  = sm;                   // [128][113]
    float* valt = sm + 128*113;         // [112][256]
    float* qs   = valt + 112*256;       // [8][132]
    float* ks   = qs + 8*132;           // [8][128]

    const int b   = blockIdx.y;
    const int n0  = blockIdx.x * 128;
    const int tid = threadIdx.x;
    const int tx  = tid & 15, ty = tid >> 4;

    const float* gvt = g_valt + (size_t)b*112*256;
    for (int i = tid; i < 112*256; i += 256) valt[i] = gvt[i];

    float acc[8][8];
#pragma unroll
    for (int i = 0; i < 8; i++)
#pragma unroll
        for (int j = 0; j < 8; j++) acc[i][j] = 0.f;

    const float* gq0 = g_q   + ((size_t)b*256)*HW + n0;
    const float* gk0 = g_key + (size_t)b*256*112;

    for (int k0 = 0; k0 < 256; k0 += 8) {
        __syncthreads();
#pragma unroll
        for (int i = 0; i < 4; i++) {
            int e = tid + 256*i; int r = e >> 7, cc = e & 127;
            qs[r*132 + cc] = gq0[(size_t)(k0 + r)*HW + cc];
        }
#pragma unroll
        for (int i = 0; i < 4; i++) {
            int e = tid + 256*i; int r = e >> 7, cc = e & 127;
            ks[r*128 + cc] = (cc < 112) ? gk0[(k0 + r)*112 + cc] : 0.f;
        }
        __syncthreads();
#pragma unroll
        for (int kk = 0; kk < 8; kk++) {
            float av[8], bv[8];
#pragma unroll
            for (int i = 0; i < 8; i++) av[i] = qs[kk*132 + tx + 16*i];
#pragma unroll
            for (int j = 0; j < 8; j++) bv[j] = ks[kk*128 + ty + 14*j];
#pragma unroll
            for (int i = 0; i < 8; i++)
#pragma unroll
                for (int j = 0; j < 8; j++)
                    acc[i][j] += av[i] * bv[j];
        }
    }
    __syncthreads();
    if (ty < 14) {
#pragma unroll
        for (int i = 0; i < 8; i++)
#pragma unroll
            for (int j = 0; j < 8; j++)
                sim[(tx + 16*i)*113 + ty + 14*j] = acc[i][j] * 0.0625f;
    }
    __syncthreads();
    if (tid < 128) {
        float* row = sim + tid*113;
        float mx = -1e30f;
        for (int s = 0; s < 110; s++) mx = fmaxf(mx, row[s]);
        float sum = 0.f;
        for (int s = 0; s < 110; s++) { float e = __expf(row[s] - mx); row[s] = e; sum += e; }
        float inv = 1.f / sum;
        for (int s = 0; s < 110; s++) row[s] *= inv;
        row[110] = 0.f; row[111] = 0.f;
    }
    __syncthreads();

    float* gctx = g_ctx + (size_t)b*256*HW + n0;
#pragma unroll
    for (int h = 0; h < 2; h++) {
#pragma unroll
        for (int i = 0; i < 8; i++)
#pragma unroll
            for (int j = 0; j < 8; j++) acc[i][j] = 0.f;
#pragma unroll 4
        for (int k = 0; k < 112; k++) {
            float av[8], bv[8];
#pragma unroll
            for (int i = 0; i < 8; i++) av[i] = sim[(tx + 16*i)*113 + k];
#pragma unroll
            for (int j = 0; j < 8; j++) bv[j] = valt[k*256 + ty + 16*j + 128*h];
#pragma unroll
            for (int i = 0; i < 8; i++)
#pragma unroll
                for (int j = 0; j < 8; j++)
                    acc[i][j] += av[i] * bv[j];
        }
#pragma unroll
        for (int j = 0; j < 8; j++) {
            int c = ty + 16*j + 128*h;
#pragma unroll
            for (int i = 0; i < 8; i++)
                gctx[(size_t)c*HW + tx + 16*i] = acc[i][j];
        }
    }
}

// ----------------------------------------------------------------------------------
extern "C" void kernel_launch(void* const* d_in, const int* in_sizes, int n_in,
                              void* d_out, int out_size)
{
    const float* feats = (const float*)d_in[0];
    const float* w_kq  = (const float*)d_in[1];
    const float* b_kq  = (const float*)d_in[2];
    const float* w_v   = (const float*)d_in[3];
    const float* b_v   = (const float*)d_in[4];
    const float* w_out = (const float*)d_in[5];
    const float* b_out = (const float*)d_in[6];
    const float* w_bot = (const float*)d_in[7];
    const float* b_bot = (const float*)d_in[8];
    float* out = (float*)d_out;

    const int pool_smem = 128*129*4;                                // 66048
    const int attn_smem = (128*113 + 112*256 + 8*132 + 8*128) * 4;  // 180864
    const int mma_smem  = 2*STAGE + 1024;                           // 136192
    cudaFuncSetAttribute(pool_kernel, cudaFuncAttributeMaxDynamicSharedMemorySize, pool_smem);
    cudaFuncSetAttribute(attn_kernel, cudaFuncAttributeMaxDynamicSharedMemorySize, attn_smem);
    cudaFuncSetAttribute(mma_gemm_kernel<0>, cudaFuncAttributeMaxDynamicSharedMemorySize, mma_smem);
    cudaFuncSetAttribute(mma_gemm_kernel<1>, cudaFuncAttributeMaxDynamicSharedMemorySize, mma_smem);

    weff_kernel<<<512, 256>>>(w_out, b_out, w_bot, b_bot);
    mma_gemm_kernel<0><<<dim3(128, 4, BATCH), 256, mma_smem>>>(feats, w_kq, b_kq, w_v, b_v, w_bot, out);
    pool_kernel<<<dim3(2, 256, BATCH), 128, pool_smem>>>();
    attn_kernel<<<dim3(128, BATCH), 256, attn_smem>>>();
    mma_gemm_kernel<1><<<dim3(128, 4, BATCH), 256, mma_smem>>>(feats, w_kq, b_kq, w_v, b_v, w_bot, out);
}

// round 9
// speedup vs baseline: 1.8230x; 1.3113x over previous
#include <cuda_runtime.h>
#include <cuda_bf16.h>
#include <cstddef>
#include <cstdint>

#define BATCH 4
#define HW 16384   // 128*128

typedef unsigned short ushort_t;

// ---------------- scratch (device globals; no allocation allowed) ----------------
__device__ float    g_q   [(size_t)BATCH*256*HW];   // 64MB  q = relu(Wkq@feats+b)
__device__ float    g_v   [(size_t)BATCH*256*HW];   // 64MB  v = Wv@feats+b
__device__ ushort_t g_ctxh[(size_t)BATCH*256*HW];   // 16MB  ctx bf16 hi
__device__ ushort_t g_ctxl[(size_t)BATCH*256*HW];   // 16MB  ctx bf16 lo
__device__ ushort_t g_fh  [(size_t)BATCH*512*HW];   // 32MB  feats bf16 hi
__device__ ushort_t g_fl  [(size_t)BATCH*512*HW];   // 32MB  feats bf16 lo
__device__ float    g_key [(size_t)BATCH*256*112];  // pooled q, padded S->112
__device__ float    g_valt[(size_t)BATCH*112*256];  // pooled v, transposed [s][c]
__device__ float    g_weff[512*256];
__device__ float    g_beff[512];
__device__ ushort_t g_A0h[512*512], g_A0l[512*512];     // [w_kq; w_v] hi/lo
__device__ ushort_t g_A1h[512*768], g_A1l[512*768];     // [Weff | Wbot_right] hi/lo

// ============================ helpers ===============================
__device__ __forceinline__ uint32_t smem_u32(const void* p) {
    uint32_t a;
    asm("{ .reg .u64 t; cvta.to.shared.u64 t, %1; cvt.u32.u64 %0, t; }" : "=r"(a) : "l"(p));
    return a;
}
__device__ __forceinline__ uint32_t swz(uint32_t o) { return o ^ ((o >> 3) & 0x70); }

__device__ __forceinline__ void ldsm4(uint32_t* r, uint32_t addr) {
    asm volatile("ldmatrix.sync.aligned.m8n8.x4.shared.b16 {%0,%1,%2,%3}, [%4];"
                 : "=r"(r[0]), "=r"(r[1]), "=r"(r[2]), "=r"(r[3]) : "r"(addr));
}
__device__ __forceinline__ void ldsm4t(uint32_t* r, uint32_t addr) {
    asm volatile("ldmatrix.sync.aligned.m8n8.x4.trans.shared.b16 {%0,%1,%2,%3}, [%4];"
                 : "=r"(r[0]), "=r"(r[1]), "=r"(r[2]), "=r"(r[3]) : "r"(addr));
}
__device__ __forceinline__ void mma16816(float* c, const uint32_t* a, uint32_t b0, uint32_t b1) {
    asm volatile(
        "mma.sync.aligned.m16n8k16.row.col.f32.bf16.bf16.f32 "
        "{%0,%1,%2,%3}, {%4,%5,%6,%7}, {%8,%9}, {%0,%1,%2,%3};"
        : "+f"(c[0]), "+f"(c[1]), "+f"(c[2]), "+f"(c[3])
        : "r"(a[0]), "r"(a[1]), "r"(a[2]), "r"(a[3]), "r"(b0), "r"(b1));
}
__device__ __forceinline__ void bf16split(float x, unsigned short& h, unsigned short& l) {
    __nv_bfloat16 hb = __float2bfloat16_rn(x);
    float r = x - __bfloat162float(hb);
    __nv_bfloat16 lb = __float2bfloat16_rn(r);
    h = __bfloat16_as_ushort(hb);
    l = __bfloat16_as_ushort(lb);
}
__device__ __forceinline__ void cp16(uint32_t s, const void* g) {
    asm volatile("cp.async.cg.shared.global [%0], [%1], 16;"
                 :: "r"(s), "l"(__cvta_generic_to_global(g)) : "memory");
}
__device__ __forceinline__ void cp_commit() {
    asm volatile("cp.async.commit_group;" ::: "memory");
}
template<int N>
__device__ __forceinline__ void cp_wait() {
    asm volatile("cp.async.wait_group %0;" :: "n"(N) : "memory");
}

// ---------------- W_eff = W_bot[:, :512] @ W_out ; b_eff = W_bot[:,:512]@b_out + b_bot
__global__ void weff_kernel(const float* __restrict__ w_out, const float* __restrict__ b_out,
                            const float* __restrict__ w_bot, const float* __restrict__ b_bot)
{
    int m = blockIdx.x;      // 0..511
    int k = threadIdx.x;     // 0..255
    float a0 = 0.f, a1 = 0.f, a2 = 0.f, a3 = 0.f;
    for (int j = 0; j < 512; j += 4) {
        a0 += w_bot[m*1024 + j + 0] * w_out[(j + 0)*256 + k];
        a1 += w_bot[m*1024 + j + 1] * w_out[(j + 1)*256 + k];
        a2 += w_bot[m*1024 + j + 2] * w_out[(j + 2)*256 + k];
        a3 += w_bot[m*1024 + j + 3] * w_out[(j + 3)*256 + k];
    }
    g_weff[m*256 + k] = (a0 + a1) + (a2 + a3);
    if (k == 0) {
        float bb = b_bot[m];
        for (int j = 0; j < 512; j++) bb += w_bot[m*1024 + j] * b_out[j];
        g_beff[m] = bb;
    }
}

// ---------------- operand pre-split kernels (fp32 -> bf16 hi/lo) ------------------
__global__ void splitA0_kernel(const float* __restrict__ w_kq, const float* __restrict__ w_v)
{
    int m = blockIdx.x;
    for (int k = threadIdx.x; k < 512; k += 256) {
        float v = (m < 256) ? w_kq[m*512 + k] : w_v[(m - 256)*512 + k];
        unsigned short h, l; bf16split(v, h, l);
        g_A0h[m*512 + k] = h; g_A0l[m*512 + k] = l;
    }
}
__global__ void splitA1_kernel(const float* __restrict__ w_bot)
{
    int m = blockIdx.x;
    for (int k = threadIdx.x; k < 768; k += 256) {
        float v = (k < 256) ? g_weff[m*256 + k] : w_bot[m*1024 + 256 + k];
        unsigned short h, l; bf16split(v, h, l);
        g_A1h[m*768 + k] = h; g_A1l[m*768 + k] = l;
    }
}
__global__ void split_feats_kernel(const float* __restrict__ f)
{
    const size_t N4 = (size_t)BATCH*512*HW/4;   // 8388608 float4s
    for (size_t t = (size_t)blockIdx.x*blockDim.x + threadIdx.x;
         t < N4; t += (size_t)gridDim.x*blockDim.x) {
        float4 v = ((const float4*)f)[t];
        unsigned short h0,h1,h2,h3,l0,l1,l2,l3;
        bf16split(v.x,h0,l0); bf16split(v.y,h1,l1);
        bf16split(v.z,h2,l2); bf16split(v.w,h3,l3);
        ((uint2*)g_fh)[t] = make_uint2((uint32_t)h0 | ((uint32_t)h1<<16),
                                       (uint32_t)h2 | ((uint32_t)h3<<16));
        ((uint2*)g_fl)[t] = make_uint2((uint32_t)l0 | ((uint32_t)l1<<16),
                                       (uint32_t)l2 | ((uint32_t)l3<<16));
    }
}

// ================= mma.sync bf16 3-split GEMM, pre-split operands =================
// 128x128 tile, 8 warps (each 64m x 32n), BK=64, 3-stage cp.async pipeline.
// A: [m][k] bf16, SW128 swizzle (128B rows). B: [k][n] bf16, 272B padded rows,
// ldmatrix.trans. acc += Ahi*Bhi; then all Ahi*Blo; then all Alo*Bhi (indep chains).
#define A_BYTES 16384          // 128 rows * 128B
#define B_BYTES 17408          // 64 rows * 272B
#define STAGE   67584          // 2*A + 2*B; also >= 128*132*4 epilogue staging

template<int MODE>
__global__ __launch_bounds__(256, 1)
void mma_gemm_kernel(const float* __restrict__ b_kq, const float* __restrict__ b_v,
                     float* __restrict__ out)
{
    constexpr int K  = (MODE == 0) ? 512 : 768;
    constexpr int NC = K / 64;
    extern __shared__ char dyn[];
    char* base = (char*)(((uintptr_t)dyn + 1023) & ~(uintptr_t)1023);

    const int tid  = threadIdx.x;
    const int wid  = tid >> 5, lane = tid & 31;
    const int wm   = wid & 1,  wn   = wid >> 1;
    const int n0   = blockIdx.x * 128;
    const int m0   = blockIdx.y * 128;
    const int b    = blockIdx.z;
    const int lr   = lane & 15, lh = lane >> 4;

    float acc[4][4][4];
#pragma unroll
    for (int i = 0; i < 4; i++)
#pragma unroll
        for (int j = 0; j < 4; j++)
#pragma unroll
            for (int r = 0; r < 4; r++) acc[i][j][r] = 0.f;

    // ---- cp.async chunk loader: bf16 gmem -> smem ----
    auto load_chunk = [&](int c) {
        uint32_t sa = smem_u32(base + (c % 3) * STAGE);
        const int k0 = c * 64;
        const ushort_t* Ah = (MODE == 0) ? g_A0h : g_A1h;
        const ushort_t* Al = (MODE == 0) ? g_A0l : g_A1l;
        const int lda = K;
#pragma unroll
        for (int u = 0; u < 4; u++) {
            int ch = tid + 256*u;             // 0..1023
            int m = ch >> 3, kc = (ch & 7) * 8;
            size_t go = (size_t)(m0 + m)*lda + k0 + kc;
            uint32_t so = swz((uint32_t)(m*128 + kc*2));
            cp16(sa + so,           Ah + go);
            cp16(sa + A_BYTES + so, Al + go);
        }
        const ushort_t *Bh, *Bl; size_t gb;
        if (MODE == 0)       { Bh = g_fh;   Bl = g_fl;   gb = ((size_t)b*512 + k0)*HW + n0; }
        else if (k0 < 256)   { Bh = g_ctxh; Bl = g_ctxl; gb = ((size_t)b*256 + k0)*HW + n0; }
        else                 { Bh = g_fh;   Bl = g_fl;   gb = ((size_t)b*512 + (k0-256))*HW + n0; }
#pragma unroll
        for (int u = 0; u < 4; u++) {
            int ch = tid + 256*u;             // 0..1023
            int k = ch >> 4, n = (ch & 15) * 8;
            size_t go = gb + (size_t)k*HW + n;
            uint32_t so = (uint32_t)(k*272 + n*2);
            cp16(sa + 2*A_BYTES + so,           Bh + go);
            cp16(sa + 2*A_BYTES + B_BYTES + so, Bl + go);
        }
    };

    // ---- compute on a resident chunk: 3 independent term passes ----
    auto compute = [&](int c) {
        uint32_t aH = smem_u32(base + (c % 3) * STAGE);
        uint32_t aL = aH + A_BYTES;
        uint32_t bH = aL + A_BYTES;
        uint32_t bL = bH + B_BYTES;
#pragma unroll
        for (int kk = 0; kk < 4; kk++) {
            const int k0 = kk * 16;
            uint32_t ah[4][4], al[4][4];
#pragma unroll
            for (int mi = 0; mi < 4; mi++) {
                int row = wm*64 + mi*16 + lr;
                uint32_t off = swz((uint32_t)(row*128 + (k0 + lh*8)*2));
                ldsm4(ah[mi], aH + off);
                ldsm4(al[mi], aL + off);
            }
            uint32_t bh[2][4], bl[2][4];
#pragma unroll
            for (int p = 0; p < 2; p++) {
                uint32_t off = (uint32_t)((k0 + lr)*272 + (wn*32 + p*16 + lh*8)*2);
                ldsm4t(bh[p], bH + off);
                ldsm4t(bl[p], bL + off);
            }
            // pass 1: Ahi*Bhi (16 independent MMAs)
#pragma unroll
            for (int mi = 0; mi < 4; mi++)
#pragma unroll
                for (int nj = 0; nj < 4; nj++) {
                    int p = nj >> 1, q = (nj & 1) * 2;
                    mma16816(acc[mi][nj], ah[mi], bh[p][q], bh[p][q+1]);
                }
            // pass 2: Ahi*Blo
#pragma unroll
            for (int mi = 0; mi < 4; mi++)
#pragma unroll
                for (int nj = 0; nj < 4; nj++) {
                    int p = nj >> 1, q = (nj & 1) * 2;
                    mma16816(acc[mi][nj], ah[mi], bl[p][q], bl[p][q+1]);
                }
            // pass 3: Alo*Bhi
#pragma unroll
            for (int mi = 0; mi < 4; mi++)
#pragma unroll
                for (int nj = 0; nj < 4; nj++) {
                    int p = nj >> 1, q = (nj & 1) * 2;
                    mma16816(acc[mi][nj], al[mi], bh[p][q], bh[p][q+1]);
                }
        }
    };

    load_chunk(0); cp_commit();
    load_chunk(1); cp_commit();
    for (int c = 0; c < NC; c++) {
        cp_wait<1>();
        __syncthreads();
        if (c + 2 < NC) { load_chunk(c + 2); cp_commit(); }
        compute(c);
    }
    __syncthreads();

    // ---- epilogue: frags -> smem [128][132] -> coalesced gmem + bias/relu ----
    float* sD = (float*)base;
    {
        int tq = lane & 3, tr = lane >> 2;
#pragma unroll
        for (int mi = 0; mi < 4; mi++)
#pragma unroll
            for (int nj = 0; nj < 4; nj++) {
                int r0 = wm*64 + mi*16 + tr;
                int cc = wn*32 + nj*8 + tq*2;
                *(float2*)&sD[(size_t)r0*132 + cc]     = make_float2(acc[mi][nj][0], acc[mi][nj][1]);
                *(float2*)&sD[(size_t)(r0+8)*132 + cc] = make_float2(acc[mi][nj][2], acc[mi][nj][3]);
            }
    }
    __syncthreads();
#pragma unroll
    for (int u = 0; u < 16; u++) {
        int idx4 = tid + 256 * u;            // 0..4095
        int m = idx4 >> 5;                   // 0..127
        int n = (idx4 & 31) * 4;
        int mg = m0 + m;
        float bias; float* dst; bool rl;
        if (MODE == 0) {
            bool isq = (mg < 256);
            bias = isq ? b_kq[mg] : b_v[mg - 256];
            dst  = isq ? (g_q + ((size_t)b*256 + mg) * HW)
                       : (g_v + ((size_t)b*256 + (mg-256)) * HW);
            rl = isq;
        } else {
            bias = g_beff[mg];
            dst  = out + ((size_t)b*512 + mg) * HW;
            rl = true;
        }
        float4 o;
        o.x = sD[(size_t)m*132 + n + 0] + bias;
        o.y = sD[(size_t)m*132 + n + 1] + bias;
        o.z = sD[(size_t)m*132 + n + 2] + bias;
        o.w = sD[(size_t)m*132 + n + 3] + bias;
        if (rl) {
            o.x = fmaxf(o.x, 0.f); o.y = fmaxf(o.y, 0.f);
            o.z = fmaxf(o.z, 0.f); o.w = fmaxf(o.w, 0.f);
        }
        *(float4*)(dst + n0 + n) = o;
    }
}

// ---------------- adaptive pooling via per-channel integral image -----------------
__global__ void pool_kernel()
{
    extern __shared__ float P[];   // [128][129]
    const int b = blockIdx.z, c = blockIdx.y, which = blockIdx.x;
    const int t = threadIdx.x;     // 0..127
    const float* src = (which == 0 ? g_q : g_v) + ((size_t)b*256 + c)*HW;

    for (int i = 0; i < 128; i++) P[i*129 + t] = src[i*128 + t];
    __syncthreads();
    { float s = 0.f;
      for (int j = 0; j < 128; j++) { s += P[t*129 + j]; P[t*129 + j] = s; } }
    __syncthreads();
    { float s = 0.f;
      for (int i = 0; i < 128; i++) { s += P[i*129 + t]; P[i*129 + t] = s; } }
    __syncthreads();
    if (t < 110) {
        int sidx = t, sc, idx;
        if      (sidx == 0) { sc = 1; idx = 0; }
        else if (sidx < 10) { sc = 3; idx = sidx - 1; }
        else if (sidx < 46) { sc = 6; idx = sidx - 10; }
        else                { sc = 8; idx = sidx - 46; }
        int i = idx / sc, j = idx % sc;
        int h0 = (i*128)/sc, h1 = ((i+1)*128 + sc - 1)/sc;
        int w0 = (j*128)/sc, w1 = ((j+1)*128 + sc - 1)/sc;
        float s11 =                      P[(h1-1)*129 + (w1-1)];
        float s01 = (h0 > 0)           ? P[(h0-1)*129 + (w1-1)] : 0.f;
        float s10 = (w0 > 0)           ? P[(h1-1)*129 + (w0-1)] : 0.f;
        float s00 = (h0 > 0 && w0 > 0) ? P[(h0-1)*129 + (w0-1)] : 0.f;
        float avg = (s11 - s01 - s10 + s00) / (float)((h1 - h0)*(w1 - w0));
        if (which == 0) g_key [((size_t)b*256 + c)*112 + sidx] = avg;
        else            g_valt[((size_t)b*112 + sidx)*256 + c] = avg;
    }
}

// ---------------- fused attention: sim GEMM -> softmax -> ctx GEMM ----------------
// ctx written directly as bf16 hi/lo (feeds GEMM1).
__global__ __launch_bounds__(256, 1)
void attn_kernel()
{
    extern __shared__ float sm[];
    float* sim  = sm;                   // [128][113]
    float* valt = sm + 128*113;         // [112][256]
    float* qs   = valt + 112*256;       // [8][132]
    float* ks   = qs + 8*132;           // [8][128]

    const int b   = blockIdx.y;
    const int n0  = blockIdx.x * 128;
    const int tid = threadIdx.x;
    const int tx  = tid & 15, ty = tid >> 4;

    const float* gvt = g_valt + (size_t)b*112*256;
    for (int i = tid; i < 112*256; i += 256) valt[i] = gvt[i];

    float acc[8][8];
#pragma unroll
    for (int i = 0; i < 8; i++)
#pragma unroll
        for (int j = 0; j < 8; j++) acc[i][j] = 0.f;

    const float* gq0 = g_q   + ((size_t)b*256)*HW + n0;
    const float* gk0 = g_key + (size_t)b*256*112;

    for (int k0 = 0; k0 < 256; k0 += 8) {
        __syncthreads();
#pragma unroll
        for (int i = 0; i < 4; i++) {
            int e = tid + 256*i; int r = e >> 7, cc = e & 127;
            qs[r*132 + cc] = gq0[(size_t)(k0 + r)*HW + cc];
        }
#pragma unroll
        for (int i = 0; i < 4; i++) {
            int e = tid + 256*i; int r = e >> 7, cc = e & 127;
            ks[r*128 + cc] = (cc < 112) ? gk0[(k0 + r)*112 + cc] : 0.f;
        }
        __syncthreads();
#pragma unroll
        for (int kk = 0; kk < 8; kk++) {
            float av[8], bv[8];
#pragma unroll
            for (int i = 0; i < 8; i++) av[i] = qs[kk*132 + tx + 16*i];
#pragma unroll
            for (int j = 0; j < 8; j++) bv[j] = ks[kk*128 + ty + 14*j];
#pragma unroll
            for (int i = 0; i < 8; i++)
#pragma unroll
                for (int j = 0; j < 8; j++)
                    acc[i][j] += av[i] * bv[j];
        }
    }
    __syncthreads();
    if (ty < 14) {
#pragma unroll
        for (int i = 0; i < 8; i++)
#pragma unroll
            for (int j = 0; j < 8; j++)
                sim[(tx + 16*i)*113 + ty + 14*j] = acc[i][j] * 0.0625f;
    }
    __syncthreads();
    if (tid < 128) {
        float* row = sim + tid*113;
        float mx = -1e30f;
        for (int s = 0; s < 110; s++) mx = fmaxf(mx, row[s]);
        float sum = 0.f;
        for (int s = 0; s < 110; s++) { float e = __expf(row[s] - mx); row[s] = e; sum += e; }
        float inv = 1.f / sum;
        for (int s = 0; s < 110; s++) row[s] *= inv;
        row[110] = 0.f; row[111] = 0.f;
    }
    __syncthreads();

    const size_t cbase = (size_t)b*256*HW + n0;
#pragma unroll
    for (int h = 0; h < 2; h++) {
#pragma unroll
        for (int i = 0; i < 8; i++)
#pragma unroll
            for (int j = 0; j < 8; j++) acc[i][j] = 0.f;
#pragma unroll 4
        for (int k = 0; k < 112; k++) {
            float av[8], bv[8];
#pragma unroll
            for (int i = 0; i < 8; i++) av[i] = sim[(tx + 16*i)*113 + k];
#pragma unroll
            for (int j = 0; j < 8; j++) bv[j] = valt[k*256 + ty + 16*j + 128*h];
#pragma unroll
            for (int i = 0; i < 8; i++)
#pragma unroll
                for (int j = 0; j < 8; j++)
                    acc[i][j] += av[i] * bv[j];
        }
#pragma unroll
        for (int j = 0; j < 8; j++) {
            int c = ty + 16*j + 128*h;
#pragma unroll
            for (int i = 0; i < 8; i++) {
                unsigned short hh, ll;
                bf16split(acc[i][j], hh, ll);
                size_t o = cbase + (size_t)c*HW + tx + 16*i;
                g_ctxh[o] = hh;
                g_ctxl[o] = ll;
            }
        }
    }
}

// ----------------------------------------------------------------------------------
extern "C" void kernel_launch(void* const* d_in, const int* in_sizes, int n_in,
                              void* d_out, int out_size)
{
    const float* feats = (const float*)d_in[0];
    const float* w_kq  = (const float*)d_in[1];
    const float* b_kq  = (const float*)d_in[2];
    const float* w_v   = (const float*)d_in[3];
    const float* b_v   = (const float*)d_in[4];
    const float* w_out = (const float*)d_in[5];
    const float* b_out = (const float*)d_in[6];
    const float* w_bot = (const float*)d_in[7];
    const float* b_bot = (const float*)d_in[8];
    float* out = (float*)d_out;

    const int pool_smem = 128*129*4;                                // 66048
    const int attn_smem = (128*113 + 112*256 + 8*132 + 8*128) * 4;  // 180864
    const int mma_smem  = 3*STAGE + 1024;                           // 203776
    cudaFuncSetAttribute(pool_kernel, cudaFuncAttributeMaxDynamicSharedMemorySize, pool_smem);
    cudaFuncSetAttribute(attn_kernel, cudaFuncAttributeMaxDynamicSharedMemorySize, attn_smem);
    cudaFuncSetAttribute(mma_gemm_kernel<0>, cudaFuncAttributeMaxDynamicSharedMemorySize, mma_smem);
    cudaFuncSetAttribute(mma_gemm_kernel<1>, cudaFuncAttributeMaxDynamicSharedMemorySize, mma_smem);

    weff_kernel<<<512, 256>>>(w_out, b_out, w_bot, b_bot);
    splitA0_kernel<<<512, 256>>>(w_kq, w_v);
    splitA1_kernel<<<512, 256>>>(w_bot);
    split_feats_kernel<<<4096, 256>>>(feats);
    mma_gemm_kernel<0><<<dim3(128, 4, BATCH), 256, mma_smem>>>(b_kq, b_v, out);
    pool_kernel<<<dim3(2, 256, BATCH), 128, pool_smem>>>();
    attn_kernel<<<dim3(128, BATCH), 256, attn_smem>>>();
    mma_gemm_kernel<1><<<dim3(128, 4, BATCH), 256, mma_smem>>>(b_kq, b_v, out);
}

// round 13
// speedup vs baseline: 2.0330x; 1.1152x over previous
#include <cuda_runtime.h>
#include <cuda_bf16.h>
#include <cstddef>
#include <cstdint>

#define BATCH 4
#define HW 16384   // 128*128

typedef unsigned short ushort_t;

// ---------------- scratch (device globals; no allocation allowed) ----------------
__device__ float    g_q   [(size_t)BATCH*256*HW];   // 64MB  q = relu(Wkq@feats+b)
__device__ float    g_v   [(size_t)BATCH*256*HW];   // 64MB  v = Wv@feats+b
__device__ ushort_t g_ctxh[(size_t)BATCH*256*HW];   // 16MB  ctx bf16 hi
__device__ ushort_t g_ctxl[(size_t)BATCH*256*HW];   // 16MB  ctx bf16 lo
__device__ ushort_t g_fh  [(size_t)BATCH*512*HW];   // 32MB  feats bf16 hi
__device__ ushort_t g_fl  [(size_t)BATCH*512*HW];   // 32MB  feats bf16 lo
__device__ float    g_key [(size_t)BATCH*256*112];  // pooled q, padded S->112
__device__ float    g_valt[(size_t)BATCH*112*256];  // pooled v, transposed [s][c]
__device__ float    g_weff[512*256];
__device__ float    g_beff[512];
__device__ ushort_t g_A0h[512*512], g_A0l[512*512];     // [w_kq; w_v] hi/lo
__device__ ushort_t g_A1h[512*768], g_A1l[512*768];     // [Weff | Wbot_right] hi/lo

// ============================ helpers ===============================
__device__ __forceinline__ uint32_t smem_u32(const void* p) {
    uint32_t a;
    asm("{ .reg .u64 t; cvta.to.shared.u64 t, %1; cvt.u32.u64 %0, t; }" : "=r"(a) : "l"(p));
    return a;
}
__device__ __forceinline__ uint32_t swz(uint32_t o) { return o ^ ((o >> 3) & 0x70); }

__device__ __forceinline__ void ldsm4(uint32_t* r, uint32_t addr) {
    asm volatile("ldmatrix.sync.aligned.m8n8.x4.shared.b16 {%0,%1,%2,%3}, [%4];"
                 : "=r"(r[0]), "=r"(r[1]), "=r"(r[2]), "=r"(r[3]) : "r"(addr));
}
__device__ __forceinline__ void ldsm4t(uint32_t* r, uint32_t addr) {
    asm volatile("ldmatrix.sync.aligned.m8n8.x4.trans.shared.b16 {%0,%1,%2,%3}, [%4];"
                 : "=r"(r[0]), "=r"(r[1]), "=r"(r[2]), "=r"(r[3]) : "r"(addr));
}
__device__ __forceinline__ void mma16816(float* c, const uint32_t* a, uint32_t b0, uint32_t b1) {
    asm volatile(
        "mma.sync.aligned.m16n8k16.row.col.f32.bf16.bf16.f32 "
        "{%0,%1,%2,%3}, {%4,%5,%6,%7}, {%8,%9}, {%0,%1,%2,%3};"
        : "+f"(c[0]), "+f"(c[1]), "+f"(c[2]), "+f"(c[3])
        : "r"(a[0]), "r"(a[1]), "r"(a[2]), "r"(a[3]), "r"(b0), "r"(b1));
}
__device__ __forceinline__ void bf16split(float x, unsigned short& h, unsigned short& l) {
    __nv_bfloat16 hb = __float2bfloat16_rn(x);
    float r = x - __bfloat162float(hb);
    __nv_bfloat16 lb = __float2bfloat16_rn(r);
    h = __bfloat16_as_ushort(hb);
    l = __bfloat16_as_ushort(lb);
}
__device__ __forceinline__ void cp16(uint32_t s, const void* g) {
    asm volatile("cp.async.cg.shared.global [%0], [%1], 16;"
                 :: "r"(s), "l"(__cvta_generic_to_global(g)) : "memory");
}
__device__ __forceinline__ void cp_commit() {
    asm volatile("cp.async.commit_group;" ::: "memory");
}
template<int N>
__device__ __forceinline__ void cp_wait() {
    asm volatile("cp.async.wait_group %0;" :: "n"(N) : "memory");
}

// ---------------- W_eff = W_bot[:, :512] @ W_out ; b_eff = W_bot[:,:512]@b_out + b_bot
__global__ void weff_kernel(const float* __restrict__ w_out, const float* __restrict__ b_out,
                            const float* __restrict__ w_bot, const float* __restrict__ b_bot)
{
    int m = blockIdx.x;      // 0..511
    int k = threadIdx.x;     // 0..255
    float a0 = 0.f, a1 = 0.f, a2 = 0.f, a3 = 0.f;
    for (int j = 0; j < 512; j += 4) {
        a0 += w_bot[m*1024 + j + 0] * w_out[(j + 0)*256 + k];
        a1 += w_bot[m*1024 + j + 1] * w_out[(j + 1)*256 + k];
        a2 += w_bot[m*1024 + j + 2] * w_out[(j + 2)*256 + k];
        a3 += w_bot[m*1024 + j + 3] * w_out[(j + 3)*256 + k];
    }
    g_weff[m*256 + k] = (a0 + a1) + (a2 + a3);
    if (k == 0) {
        float bb = b_bot[m];
        for (int j = 0; j < 512; j++) bb += w_bot[m*1024 + j] * b_out[j];
        g_beff[m] = bb;
    }
}

// ---------------- operand pre-split kernels (fp32 -> bf16 hi/lo) ------------------
__global__ void splitA0_kernel(const float* __restrict__ w_kq, const float* __restrict__ w_v)
{
    int m = blockIdx.x;
    for (int k = threadIdx.x; k < 512; k += 256) {
        float v = (m < 256) ? w_kq[m*512 + k] : w_v[(m - 256)*512 + k];
        unsigned short h, l; bf16split(v, h, l);
        g_A0h[m*512 + k] = h; g_A0l[m*512 + k] = l;
    }
}
__global__ void splitA1_kernel(const float* __restrict__ w_bot)
{
    int m = blockIdx.x;
    for (int k = threadIdx.x; k < 768; k += 256) {
        float v = (k < 256) ? g_weff[m*256 + k] : w_bot[m*1024 + 256 + k];
        unsigned short h, l; bf16split(v, h, l);
        g_A1h[m*768 + k] = h; g_A1l[m*768 + k] = l;
    }
}
__global__ void split_feats_kernel(const float* __restrict__ f)
{
    const size_t N4 = (size_t)BATCH*512*HW/4;
    for (size_t t = (size_t)blockIdx.x*blockDim.x + threadIdx.x;
         t < N4; t += (size_t)gridDim.x*blockDim.x) {
        float4 v = ((const float4*)f)[t];
        unsigned short h0,h1,h2,h3,l0,l1,l2,l3;
        bf16split(v.x,h0,l0); bf16split(v.y,h1,l1);
        bf16split(v.z,h2,l2); bf16split(v.w,h3,l3);
        ((uint2*)g_fh)[t] = make_uint2((uint32_t)h0 | ((uint32_t)h1<<16),
                                       (uint32_t)h2 | ((uint32_t)h3<<16));
        ((uint2*)g_fl)[t] = make_uint2((uint32_t)l0 | ((uint32_t)l1<<16),
                                       (uint32_t)l2 | ((uint32_t)l3<<16));
    }
}

// ================= mma.sync bf16 3-split GEMM, pre-split operands =================
// CTA tile 128m x 256n, 16 warps (each 64m x 32n), BK=64, 2-stage cp.async.
// A: [m][k] bf16, SW128 swizzle (128B rows). B: [k][n] bf16, 528B padded rows.
#define A_BYTES 16384           // 128 rows * 128B
#define B_ROW   528             // 256 bf16 * 2B + 16 pad
#define B_BYTES (64*B_ROW)      // 33792
#define STAGE   (2*A_BYTES + 2*B_BYTES)   // 100352

template<int MODE>
__global__ __launch_bounds__(512, 1)
void mma_gemm_kernel(const float* __restrict__ b_kq, const float* __restrict__ b_v,
                     float* __restrict__ out)
{
    constexpr int K  = (MODE == 0) ? 512 : 768;
    constexpr int NC = K / 64;
    extern __shared__ char dyn[];
    char* base = (char*)(((uintptr_t)dyn + 1023) & ~(uintptr_t)1023);

    const int tid  = threadIdx.x;
    const int wid  = tid >> 5, lane = tid & 31;
    const int wm   = wid & 1,  wn   = wid >> 1;       // wn 0..7
    const int m0   = blockIdx.x * 128;                // x = m-tile (L2 reuse of B)
    const int n0   = blockIdx.y * 256;
    const int b    = blockIdx.z;
    const int lr   = lane & 15, lh = lane >> 4;

    float acc[4][4][4];
#pragma unroll
    for (int i = 0; i < 4; i++)
#pragma unroll
        for (int j = 0; j < 4; j++)
#pragma unroll
            for (int r = 0; r < 4; r++) acc[i][j][r] = 0.f;

    auto load_chunk = [&](int c) {
        uint32_t sa = smem_u32(base + (c & 1) * STAGE);
        const int k0 = c * 64;
        const ushort_t* Ah = (MODE == 0) ? g_A0h : g_A1h;
        const ushort_t* Al = (MODE == 0) ? g_A0l : g_A1l;
#pragma unroll
        for (int u = 0; u < 2; u++) {
            int ch = tid + 512*u;             // 0..1023
            int m = ch >> 3, kc = (ch & 7) * 8;
            size_t go = (size_t)(m0 + m)*K + k0 + kc;
            uint32_t so = swz((uint32_t)(m*128 + kc*2));
            cp16(sa + so,           Ah + go);
            cp16(sa + A_BYTES + so, Al + go);
        }
        const ushort_t *Bh, *Bl; size_t gb;
        if (MODE == 0)       { Bh = g_fh;   Bl = g_fl;   gb = ((size_t)b*512 + k0)*HW + n0; }
        else if (k0 < 256)   { Bh = g_ctxh; Bl = g_ctxl; gb = ((size_t)b*256 + k0)*HW + n0; }
        else                 { Bh = g_fh;   Bl = g_fl;   gb = ((size_t)b*512 + (k0-256))*HW + n0; }
#pragma unroll
        for (int u = 0; u < 2; u++) {
            int ch = tid + 512*u;             // 0..1023
            int k = ch >> 4, n = (ch & 15) * 16;
            size_t go = gb + (size_t)k*HW + n;
            uint32_t so = (uint32_t)(k*B_ROW + n*2);
            cp16(sa + 2*A_BYTES + so,                Bh + go);
            cp16(sa + 2*A_BYTES + so + 16,           Bh + go + 8);
            cp16(sa + 2*A_BYTES + B_BYTES + so,      Bl + go);
            cp16(sa + 2*A_BYTES + B_BYTES + so + 16, Bl + go + 8);
        }
    };

    auto compute = [&](int c) {
        uint32_t aH = smem_u32(base + (c & 1) * STAGE);
        uint32_t aL = aH + A_BYTES;
        uint32_t bH = aL + A_BYTES;
        uint32_t bL = bH + B_BYTES;
#pragma unroll
        for (int kk = 0; kk < 4; kk++) {
            const int k0 = kk * 16;
            uint32_t ah[4][4], al[4][4];
#pragma unroll
            for (int mi = 0; mi < 4; mi++) {
                int row = wm*64 + mi*16 + lr;
                uint32_t off = swz((uint32_t)(row*128 + (k0 + lh*8)*2));
                ldsm4(ah[mi], aH + off);
                ldsm4(al[mi], aL + off);
            }
            uint32_t bh[2][4], bl[2][4];
#pragma unroll
            for (int p = 0; p < 2; p++) {
                uint32_t off = (uint32_t)((k0 + lr)*B_ROW + (wn*32 + p*16 + lh*8)*2);
                ldsm4t(bh[p], bH + off);
                ldsm4t(bl[p], bL + off);
            }
#pragma unroll
            for (int mi = 0; mi < 4; mi++)
#pragma unroll
                for (int nj = 0; nj < 4; nj++) {
                    int p = nj >> 1, q = (nj & 1) * 2;
                    mma16816(acc[mi][nj], ah[mi], bh[p][q], bh[p][q+1]);
                }
#pragma unroll
            for (int mi = 0; mi < 4; mi++)
#pragma unroll
                for (int nj = 0; nj < 4; nj++) {
                    int p = nj >> 1, q = (nj & 1) * 2;
                    mma16816(acc[mi][nj], ah[mi], bl[p][q], bl[p][q+1]);
                }
#pragma unroll
            for (int mi = 0; mi < 4; mi++)
#pragma unroll
                for (int nj = 0; nj < 4; nj++) {
                    int p = nj >> 1, q = (nj & 1) * 2;
                    mma16816(acc[mi][nj], al[mi], bh[p][q], bh[p][q+1]);
                }
        }
    };

    load_chunk(0); cp_commit();
    for (int c = 0; c < NC; c++) {
        if (c + 1 < NC) { load_chunk(c + 1); cp_commit(); cp_wait<1>(); }
        else            { cp_wait<0>(); }
        __syncthreads();
        compute(c);
        __syncthreads();
    }

    // ---- epilogue: frags -> smem [128][260] -> coalesced gmem + bias/relu ----
    float* sD = (float*)base;
    {
        int tq = lane & 3, tr = lane >> 2;
#pragma unroll
        for (int mi = 0; mi < 4; mi++)
#pragma unroll
            for (int nj = 0; nj < 4; nj++) {
                int r0 = wm*64 + mi*16 + tr;
                int cc = wn*32 + nj*8 + tq*2;
                *(float2*)&sD[(size_t)r0*260 + cc]     = make_float2(acc[mi][nj][0], acc[mi][nj][1]);
                *(float2*)&sD[(size_t)(r0+8)*260 + cc] = make_float2(acc[mi][nj][2], acc[mi][nj][3]);
            }
    }
    __syncthreads();
#pragma unroll
    for (int u = 0; u < 16; u++) {
        int idx4 = tid + 512 * u;            // 0..8191
        int m = idx4 >> 6;                   // 0..127
        int n = (idx4 & 63) * 4;             // 0..252
        int mg = m0 + m;
        float bias; float* dst; bool rl;
        if (MODE == 0) {
            bool isq = (mg < 256);
            bias = isq ? b_kq[mg] : b_v[mg - 256];
            dst  = isq ? (g_q + ((size_t)b*256 + mg) * HW)
                       : (g_v + ((size_t)b*256 + (mg-256)) * HW);
            rl = isq;
        } else {
            bias = g_beff[mg];
            dst  = out + ((size_t)b*512 + mg) * HW;
            rl = true;
        }
        float4 o;
        o.x = sD[(size_t)m*260 + n + 0] + bias;
        o.y = sD[(size_t)m*260 + n + 1] + bias;
        o.z = sD[(size_t)m*260 + n + 2] + bias;
        o.w = sD[(size_t)m*260 + n + 3] + bias;
        if (rl) {
            o.x = fmaxf(o.x, 0.f); o.y = fmaxf(o.y, 0.f);
            o.z = fmaxf(o.z, 0.f); o.w = fmaxf(o.w, 0.f);
        }
        *(float4*)(dst + n0 + n) = o;
    }
}

// ---------------- adaptive pooling via per-channel integral image -----------------
__global__ void pool_kernel()
{
    extern __shared__ float P[];   // [128][129]
    const int b = blockIdx.z, c = blockIdx.y, which = blockIdx.x;
    const int t = threadIdx.x;     // 0..127
    const float* src = (which == 0 ? g_q : g_v) + ((size_t)b*256 + c)*HW;

    for (int i = 0; i < 128; i++) P[i*129 + t] = src[i*128 + t];
    __syncthreads();
    { float s = 0.f;
      for (int j = 0; j < 128; j++) { s += P[t*129 + j]; P[t*129 + j] = s; } }
    __syncthreads();
    { float s = 0.f;
      for (int i = 0; i < 128; i++) { s += P[i*129 + t]; P[i*129 + t] = s; } }
    __syncthreads();
    if (t < 110) {
        int sidx = t, sc, idx;
        if      (sidx == 0) { sc = 1; idx = 0; }
        else if (sidx < 10) { sc = 3; idx = sidx - 1; }
        else if (sidx < 46) { sc = 6; idx = sidx - 10; }
        else                { sc = 8; idx = sidx - 46; }
        int i = idx / sc, j = idx % sc;
        int h0 = (i*128)/sc, h1 = ((i+1)*128 + sc - 1)/sc;
        int w0 = (j*128)/sc, w1 = ((j+1)*128 + sc - 1)/sc;
        float s11 =                      P[(h1-1)*129 + (w1-1)];
        float s01 = (h0 > 0)           ? P[(h0-1)*129 + (w1-1)] : 0.f;
        float s10 = (w0 > 0)           ? P[(h1-1)*129 + (w0-1)] : 0.f;
        float s00 = (h0 > 0 && w0 > 0) ? P[(h0-1)*129 + (w0-1)] : 0.f;
        float avg = (s11 - s01 - s10 + s00) / (float)((h1 - h0)*(w1 - w0));
        if (which == 0) g_key [((size_t)b*256 + c)*112 + sidx] = avg;
        else            g_valt[((size_t)b*112 + sidx)*256 + c] = avg;
    }
}

// ---------------- fused attention: cp.async streamed sim -> softmax -> ctx --------
// ctx written directly as bf16 hi/lo (feeds GEMM1).
__global__ __launch_bounds__(256, 1)
void attn_kernel()
{
    extern __shared__ float sm[];
    float* sim  = sm;                   // [128][113]          14464 floats
    float* valt = sm + 128*113;         // [112][256]          28672 floats
    float* st   = valt + 112*256;       // 2 stages * (8*132 qs + 8*128 ks)

    const int b   = blockIdx.y;
    const int n0  = blockIdx.x * 128;
    const int tid = threadIdx.x;
    const int tx  = tid & 15, ty = tid >> 4;

    const float* gvt = g_valt + (size_t)b*112*256;
    const float* gq0 = g_q   + ((size_t)b*256)*HW + n0;
    const float* gk0 = g_key + (size_t)b*256*112;

    // valt via cp.async (group 0) — overlapped with entire sim phase
    {
        uint32_t vs = smem_u32(valt);
        #pragma unroll
        for (int u = 0; u < 28; u++) {
            int idx = tid + 256*u;   // 0..7167 16B chunks
            cp16(vs + idx*16, gvt + idx*4);
        }
        cp_commit();
    }
    // zero ks pads of both stages (cols 112..127)
    {
        int s = tid >> 7, r = (tid >> 4) & 7, c2 = 112 + (tid & 15);
        st[s*2080 + 8*132 + r*128 + c2] = 0.f;
    }

    auto load_stage = [&](int c) {
        int s = c & 1;
        uint32_t qs_s = smem_u32(st + s*2080);
        uint32_t ks_s = qs_s + 8*132*4;
        int k0 = c * 8;
        { // qs: 8 rows x 128 floats = 256 cp16 -> 1 per thread
            int r = tid >> 5, cc = (tid & 31) * 4;
            cp16(qs_s + (r*132 + cc)*4, gq0 + (size_t)(k0 + r)*HW + cc);
        }
        { // ks: 8 rows x 112 floats = 224 cp16
            int r = tid >> 5, cc = (tid & 31) * 4;
            if ((tid & 31) < 28)
                cp16(ks_s + (r*128 + cc)*4, gk0 + (k0 + r)*112 + cc);
        }
        cp_commit();
    };

    float acc[8][8];
#pragma unroll
    for (int i = 0; i < 8; i++)
#pragma unroll
        for (int j = 0; j < 8; j++) acc[i][j] = 0.f;

    load_stage(0);
    for (int c = 0; c < 32; c++) {
        if (c + 1 < 32) { load_stage(c + 1); cp_wait<1>(); }
        else            { cp_wait<0>(); }
        __syncthreads();
        const float* qs = st + (c & 1)*2080;
        const float* ks = qs + 8*132;
#pragma unroll
        for (int kk = 0; kk < 8; kk++) {
            float av[8], bv[8];
#pragma unroll
            for (int i = 0; i < 8; i++) av[i] = qs[kk*132 + tx + 16*i];
#pragma unroll
            for (int j = 0; j < 8; j++) bv[j] = ks[kk*128 + ty + 14*j];
#pragma unroll
            for (int i = 0; i < 8; i++)
#pragma unroll
                for (int j = 0; j < 8; j++)
                    acc[i][j] += av[i] * bv[j];
        }
        __syncthreads();
    }
    if (ty < 14) {
#pragma unroll
        for (int i = 0; i < 8; i++)
#pragma unroll
            for (int j = 0; j < 8; j++)
                sim[(tx + 16*i)*113 + ty + 14*j] = acc[i][j] * 0.0625f;
    }
    __syncthreads();
    // softmax: 2 threads per row (55 + 55 of the 110), shfl combine
    {
        int row = tid >> 1, half = tid & 1;
        float* r = sim + row*113;
        int s0 = half*55, s1 = s0 + 55;
        float mx = -1e30f;
        for (int s = s0; s < s1; s++) mx = fmaxf(mx, r[s]);
        mx = fmaxf(mx, __shfl_xor_sync(0xFFFFFFFFu, mx, 1));
        float sum = 0.f;
        for (int s = s0; s < s1; s++) { float e = __expf(r[s] - mx); r[s] = e; sum += e; }
        sum += __shfl_xor_sync(0xFFFFFFFFu, sum, 1);
        float inv = 1.f / sum;
        for (int s = s0; s < s1; s++) r[s] *= inv;
        if (half == 0) { r[110] = 0.f; r[111] = 0.f; }
    }
    __syncthreads();

    const size_t cbase = (size_t)b*256*HW + n0;
#pragma unroll
    for (int h = 0; h < 2; h++) {
#pragma unroll
        for (int i = 0; i < 8; i++)
#pragma unroll
            for (int j = 0; j < 8; j++) acc[i][j] = 0.f;
#pragma unroll 4
        for (int k = 0; k < 112; k++) {
            float av[8], bv[8];
#pragma unroll
            for (int i = 0; i < 8; i++) av[i] = sim[(tx + 16*i)*113 + k];
#pragma unroll
            for (int j = 0; j < 8; j++) bv[j] = valt[k*256 + ty + 16*j + 128*h];
#pragma unroll
            for (int i = 0; i < 8; i++)
#pragma unroll
                for (int j = 0; j < 8; j++)
                    acc[i][j] += av[i] * bv[j];
        }
#pragma unroll
        for (int j = 0; j < 8; j++) {
            int c = ty + 16*j + 128*h;
#pragma unroll
            for (int i = 0; i < 8; i++) {
                unsigned short hh, ll;
                bf16split(acc[i][j], hh, ll);
                size_t o = cbase + (size_t)c*HW + tx + 16*i;
                g_ctxh[o] = hh;
                g_ctxl[o] = ll;
            }
        }
    }
}

// ----------------------------------------------------------------------------------
extern "C" void kernel_launch(void* const* d_in, const int* in_sizes, int n_in,
                              void* d_out, int out_size)
{
    const float* w_kq  = (const float*)d_in[1];
    const float* b_kq  = (const float*)d_in[2];
    const float* w_v   = (const float*)d_in[3];
    const float* b_v   = (const float*)d_in[4];
    const float* w_out = (const float*)d_in[5];
    const float* b_out = (const float*)d_in[6];
    const float* w_bot = (const float*)d_in[7];
    const float* b_bot = (const float*)d_in[8];
    const float* feats = (const float*)d_in[0];
    float* out = (float*)d_out;

    const int pool_smem = 128*129*4;                                   // 66048
    const int attn_smem = (128*113 + 112*256 + 2*2080) * 4;            // 189184
    const int mma_smem  = 2*STAGE + 1024;                              // 201728
    cudaFuncSetAttribute(pool_kernel, cudaFuncAttributeMaxDynamicSharedMemorySize, pool_smem);
    cudaFuncSetAttribute(attn_kernel, cudaFuncAttributeMaxDynamicSharedMemorySize, attn_smem);
    cudaFuncSetAttribute(mma_gemm_kernel<0>, cudaFuncAttributeMaxDynamicSharedMemorySize, mma_smem);
    cudaFuncSetAttribute(mma_gemm_kernel<1>, cudaFuncAttributeMaxDynamicSharedMemorySize, mma_smem);

    weff_kernel<<<512, 256>>>(w_out, b_out, w_bot, b_bot);
    splitA0_kernel<<<512, 256>>>(w_kq, w_v);
    splitA1_kernel<<<512, 256>>>(w_bot);
    split_feats_kernel<<<4096, 256>>>(feats);
    mma_gemm_kernel<0><<<dim3(4, 64, BATCH), 512, mma_smem>>>(b_kq, b_v, out);
    pool_kernel<<<dim3(2, 256, BATCH), 128, pool_smem>>>();
    attn_kernel<<<dim3(128, BATCH), 256, attn_smem>>>();
    mma_gemm_kernel<1><<<dim3(4, 64, BATCH), 512, mma_smem>>>(b_kq, b_v, out);
}

// round 14
// speedup vs baseline: 2.1554x; 1.0602x over previous
#include <cuda_runtime.h>
#include <cuda_bf16.h>
#include <cstddef>
#include <cstdint>

#define BATCH 4
#define HW 16384   // 128*128

typedef unsigned short ushort_t;

// ---------------- scratch (device globals; no allocation allowed) ----------------
__device__ float    g_q   [(size_t)BATCH*256*HW];   // 64MB  q fp32 (pool input)
__device__ float    g_v   [(size_t)BATCH*256*HW];   // 64MB  v fp32 (pool input)
__device__ ushort_t g_qh  [(size_t)BATCH*256*HW];   // 32MB  q bf16 hi (attn input)
__device__ ushort_t g_ql  [(size_t)BATCH*256*HW];   // 32MB  q bf16 lo
__device__ ushort_t g_ctxh[(size_t)BATCH*256*HW];   // 16MB  ctx bf16 hi
__device__ ushort_t g_ctxl[(size_t)BATCH*256*HW];   // 16MB  ctx bf16 lo
__device__ ushort_t g_fh  [(size_t)BATCH*512*HW];   // 32MB  feats bf16 hi
__device__ ushort_t g_fl  [(size_t)BATCH*512*HW];   // 32MB  feats bf16 lo
__device__ ushort_t g_keyh[(size_t)BATCH*256*112];  // pooled q bf16 hi [c][112]
__device__ ushort_t g_keyl[(size_t)BATCH*256*112];
__device__ ushort_t g_valth[(size_t)BATCH*112*256]; // pooled v bf16 hi [s][c]
__device__ ushort_t g_valtl[(size_t)BATCH*112*256];
__device__ float    g_weff[512*256];
__device__ float    g_beff[512];
__device__ ushort_t g_A0h[512*512], g_A0l[512*512];     // [w_kq; w_v] hi/lo
__device__ ushort_t g_A1h[512*768], g_A1l[512*768];     // [Weff | Wbot_right] hi/lo

// ============================ helpers ===============================
__device__ __forceinline__ uint32_t smem_u32(const void* p) {
    uint32_t a;
    asm("{ .reg .u64 t; cvta.to.shared.u64 t, %1; cvt.u32.u64 %0, t; }" : "=r"(a) : "l"(p));
    return a;
}
__device__ __forceinline__ uint32_t swz(uint32_t o) { return o ^ ((o >> 3) & 0x70); }

__device__ __forceinline__ void ldsm4(uint32_t* r, uint32_t addr) {
    asm volatile("ldmatrix.sync.aligned.m8n8.x4.shared.b16 {%0,%1,%2,%3}, [%4];"
                 : "=r"(r[0]), "=r"(r[1]), "=r"(r[2]), "=r"(r[3]) : "r"(addr));
}
__device__ __forceinline__ void ldsm4t(uint32_t* r, uint32_t addr) {
    asm volatile("ldmatrix.sync.aligned.m8n8.x4.trans.shared.b16 {%0,%1,%2,%3}, [%4];"
                 : "=r"(r[0]), "=r"(r[1]), "=r"(r[2]), "=r"(r[3]) : "r"(addr));
}
__device__ __forceinline__ void mma16816(float* c, const uint32_t* a, uint32_t b0, uint32_t b1) {
    asm volatile(
        "mma.sync.aligned.m16n8k16.row.col.f32.bf16.bf16.f32 "
        "{%0,%1,%2,%3}, {%4,%5,%6,%7}, {%8,%9}, {%0,%1,%2,%3};"
        : "+f"(c[0]), "+f"(c[1]), "+f"(c[2]), "+f"(c[3])
        : "r"(a[0]), "r"(a[1]), "r"(a[2]), "r"(a[3]), "r"(b0), "r"(b1));
}
__device__ __forceinline__ void bf16split(float x, unsigned short& h, unsigned short& l) {
    __nv_bfloat16 hb = __float2bfloat16_rn(x);
    float r = x - __bfloat162float(hb);
    __nv_bfloat16 lb = __float2bfloat16_rn(r);
    h = __bfloat16_as_ushort(hb);
    l = __bfloat16_as_ushort(lb);
}
__device__ __forceinline__ void cp16(uint32_t s, const void* g) {
    asm volatile("cp.async.cg.shared.global [%0], [%1], 16;"
                 :: "r"(s), "l"(__cvta_generic_to_global(g)) : "memory");
}
__device__ __forceinline__ void cp_commit() {
    asm volatile("cp.async.commit_group;" ::: "memory");
}
template<int N>
__device__ __forceinline__ void cp_wait() {
    asm volatile("cp.async.wait_group %0;" :: "n"(N) : "memory");
}

// ---------------- W_eff = W_bot[:, :512] @ W_out ; b_eff = W_bot[:,:512]@b_out + b_bot
__global__ void weff_kernel(const float* __restrict__ w_out, const float* __restrict__ b_out,
                            const float* __restrict__ w_bot, const float* __restrict__ b_bot)
{
    int m = blockIdx.x;      // 0..511
    int k = threadIdx.x;     // 0..255
    float a0 = 0.f, a1 = 0.f, a2 = 0.f, a3 = 0.f;
    for (int j = 0; j < 512; j += 4) {
        a0 += w_bot[m*1024 + j + 0] * w_out[(j + 0)*256 + k];
        a1 += w_bot[m*1024 + j + 1] * w_out[(j + 1)*256 + k];
        a2 += w_bot[m*1024 + j + 2] * w_out[(j + 2)*256 + k];
        a3 += w_bot[m*1024 + j + 3] * w_out[(j + 3)*256 + k];
    }
    g_weff[m*256 + k] = (a0 + a1) + (a2 + a3);
    if (k == 0) {
        float bb = b_bot[m];
        for (int j = 0; j < 512; j++) bb += w_bot[m*1024 + j] * b_out[j];
        g_beff[m] = bb;
    }
}

// ---------------- operand pre-split kernels (fp32 -> bf16 hi/lo) ------------------
__global__ void splitA0_kernel(const float* __restrict__ w_kq, const float* __restrict__ w_v)
{
    int m = blockIdx.x;
    for (int k = threadIdx.x; k < 512; k += 256) {
        float v = (m < 256) ? w_kq[m*512 + k] : w_v[(m - 256)*512 + k];
        unsigned short h, l; bf16split(v, h, l);
        g_A0h[m*512 + k] = h; g_A0l[m*512 + k] = l;
    }
}
__global__ void splitA1_kernel(const float* __restrict__ w_bot)
{
    int m = blockIdx.x;
    for (int k = threadIdx.x; k < 768; k += 256) {
        float v = (k < 256) ? g_weff[m*256 + k] : w_bot[m*1024 + 256 + k];
        unsigned short h, l; bf16split(v, h, l);
        g_A1h[m*768 + k] = h; g_A1l[m*768 + k] = l;
    }
}
__global__ void split_feats_kernel(const float* __restrict__ f)
{
    const size_t N4 = (size_t)BATCH*512*HW/4;
    for (size_t t = (size_t)blockIdx.x*blockDim.x + threadIdx.x;
         t < N4; t += (size_t)gridDim.x*blockDim.x) {
        float4 v = ((const float4*)f)[t];
        unsigned short h0,h1,h2,h3,l0,l1,l2,l3;
        bf16split(v.x,h0,l0); bf16split(v.y,h1,l1);
        bf16split(v.z,h2,l2); bf16split(v.w,h3,l3);
        ((uint2*)g_fh)[t] = make_uint2((uint32_t)h0 | ((uint32_t)h1<<16),
                                       (uint32_t)h2 | ((uint32_t)h3<<16));
        ((uint2*)g_fl)[t] = make_uint2((uint32_t)l0 | ((uint32_t)l1<<16),
                                       (uint32_t)l2 | ((uint32_t)l3<<16));
    }
}

// ================= mma.sync bf16 3-split GEMM, pre-split operands =================
#define A_BYTES 16384           // 128 rows * 128B
#define B_ROW   528             // 256 bf16 * 2B + 16 pad
#define B_BYTES (64*B_ROW)      // 33792
#define STAGE   (2*A_BYTES + 2*B_BYTES)   // 100352

template<int MODE>
__global__ __launch_bounds__(512, 1)
void mma_gemm_kernel(const float* __restrict__ b_kq, const float* __restrict__ b_v,
                     float* __restrict__ out)
{
    constexpr int K  = (MODE == 0) ? 512 : 768;
    constexpr int NC = K / 64;
    extern __shared__ char dyn[];
    char* base = (char*)(((uintptr_t)dyn + 1023) & ~(uintptr_t)1023);

    const int tid  = threadIdx.x;
    const int wid  = tid >> 5, lane = tid & 31;
    const int wm   = wid & 1,  wn   = wid >> 1;       // wn 0..7
    const int m0   = blockIdx.x * 128;                // x = m-tile (L2 reuse of B)
    const int n0   = blockIdx.y * 256;
    const int b    = blockIdx.z;
    const int lr   = lane & 15, lh = lane >> 4;

    float acc[4][4][4];
#pragma unroll
    for (int i = 0; i < 4; i++)
#pragma unroll
        for (int j = 0; j < 4; j++)
#pragma unroll
            for (int r = 0; r < 4; r++) acc[i][j][r] = 0.f;

    auto load_chunk = [&](int c) {
        uint32_t sa = smem_u32(base + (c & 1) * STAGE);
        const int k0 = c * 64;
        const ushort_t* Ah = (MODE == 0) ? g_A0h : g_A1h;
        const ushort_t* Al = (MODE == 0) ? g_A0l : g_A1l;
#pragma unroll
        for (int u = 0; u < 2; u++) {
            int ch = tid + 512*u;             // 0..1023
            int m = ch >> 3, kc = (ch & 7) * 8;
            size_t go = (size_t)(m0 + m)*K + k0 + kc;
            uint32_t so = swz((uint32_t)(m*128 + kc*2));
            cp16(sa + so,           Ah + go);
            cp16(sa + A_BYTES + so, Al + go);
        }
        const ushort_t *Bh, *Bl; size_t gb;
        if (MODE == 0)       { Bh = g_fh;   Bl = g_fl;   gb = ((size_t)b*512 + k0)*HW + n0; }
        else if (k0 < 256)   { Bh = g_ctxh; Bl = g_ctxl; gb = ((size_t)b*256 + k0)*HW + n0; }
        else                 { Bh = g_fh;   Bl = g_fl;   gb = ((size_t)b*512 + (k0-256))*HW + n0; }
#pragma unroll
        for (int u = 0; u < 2; u++) {
            int ch = tid + 512*u;             // 0..1023
            int k = ch >> 4, n = (ch & 15) * 16;
            size_t go = gb + (size_t)k*HW + n;
            uint32_t so = (uint32_t)(k*B_ROW + n*2);
            cp16(sa + 2*A_BYTES + so,                Bh + go);
            cp16(sa + 2*A_BYTES + so + 16,           Bh + go + 8);
            cp16(sa + 2*A_BYTES + B_BYTES + so,      Bl + go);
            cp16(sa + 2*A_BYTES + B_BYTES + so + 16, Bl + go + 8);
        }
    };

    auto compute = [&](int c) {
        uint32_t aH = smem_u32(base + (c & 1) * STAGE);
        uint32_t aL = aH + A_BYTES;
        uint32_t bH = aL + A_BYTES;
        uint32_t bL = bH + B_BYTES;
#pragma unroll
        for (int kk = 0; kk < 4; kk++) {
            const int k0 = kk * 16;
            uint32_t ah[4][4], al[4][4];
#pragma unroll
            for (int mi = 0; mi < 4; mi++) {
                int row = wm*64 + mi*16 + lr;
                uint32_t off = swz((uint32_t)(row*128 + (k0 + lh*8)*2));
                ldsm4(ah[mi], aH + off);
                ldsm4(al[mi], aL + off);
            }
            uint32_t bh[2][4], bl[2][4];
#pragma unroll
            for (int p = 0; p < 2; p++) {
                uint32_t off = (uint32_t)((k0 + lr)*B_ROW + (wn*32 + p*16 + lh*8)*2);
                ldsm4t(bh[p], bH + off);
                ldsm4t(bl[p], bL + off);
            }
#pragma unroll
            for (int mi = 0; mi < 4; mi++)
#pragma unroll
                for (int nj = 0; nj < 4; nj++) {
                    int p = nj >> 1, q = (nj & 1) * 2;
                    mma16816(acc[mi][nj], ah[mi], bh[p][q], bh[p][q+1]);
                }
#pragma unroll
            for (int mi = 0; mi < 4; mi++)
#pragma unroll
                for (int nj = 0; nj < 4; nj++) {
                    int p = nj >> 1, q = (nj & 1) * 2;
                    mma16816(acc[mi][nj], ah[mi], bl[p][q], bl[p][q+1]);
                }
#pragma unroll
            for (int mi = 0; mi < 4; mi++)
#pragma unroll
                for (int nj = 0; nj < 4; nj++) {
                    int p = nj >> 1, q = (nj & 1) * 2;
                    mma16816(acc[mi][nj], al[mi], bh[p][q], bh[p][q+1]);
                }
        }
    };

    load_chunk(0); cp_commit();
    for (int c = 0; c < NC; c++) {
        if (c + 1 < NC) { load_chunk(c + 1); cp_commit(); cp_wait<1>(); }
        else            { cp_wait<0>(); }
        __syncthreads();
        compute(c);
        __syncthreads();
    }

    // ---- epilogue: frags -> smem [128][260] -> coalesced gmem + bias/relu ----
    float* sD = (float*)base;
    {
        int tq = lane & 3, tr = lane >> 2;
#pragma unroll
        for (int mi = 0; mi < 4; mi++)
#pragma unroll
            for (int nj = 0; nj < 4; nj++) {
                int r0 = wm*64 + mi*16 + tr;
                int cc = wn*32 + nj*8 + tq*2;
                *(float2*)&sD[(size_t)r0*260 + cc]     = make_float2(acc[mi][nj][0], acc[mi][nj][1]);
                *(float2*)&sD[(size_t)(r0+8)*260 + cc] = make_float2(acc[mi][nj][2], acc[mi][nj][3]);
            }
    }
    __syncthreads();
#pragma unroll
    for (int u = 0; u < 16; u++) {
        int idx4 = tid + 512 * u;            // 0..8191
        int m = idx4 >> 6;                   // 0..127
        int n = (idx4 & 63) * 4;             // 0..252
        int mg = m0 + m;
        float bias; float* dst; bool rl; bool isq = false;
        if (MODE == 0) {
            isq = (mg < 256);
            bias = isq ? b_kq[mg] : b_v[mg - 256];
            dst  = isq ? (g_q + ((size_t)b*256 + mg) * HW)
                       : (g_v + ((size_t)b*256 + (mg-256)) * HW);
            rl = isq;
        } else {
            bias = g_beff[mg];
            dst  = out + ((size_t)b*512 + mg) * HW;
            rl = true;
        }
        float4 o;
        o.x = sD[(size_t)m*260 + n + 0] + bias;
        o.y = sD[(size_t)m*260 + n + 1] + bias;
        o.z = sD[(size_t)m*260 + n + 2] + bias;
        o.w = sD[(size_t)m*260 + n + 3] + bias;
        if (rl) {
            o.x = fmaxf(o.x, 0.f); o.y = fmaxf(o.y, 0.f);
            o.z = fmaxf(o.z, 0.f); o.w = fmaxf(o.w, 0.f);
        }
        *(float4*)(dst + n0 + n) = o;
        if (MODE == 0 && isq) {
            unsigned short h0,l0,h1,l1,h2,l2,h3,l3;
            bf16split(o.x,h0,l0); bf16split(o.y,h1,l1);
            bf16split(o.z,h2,l2); bf16split(o.w,h3,l3);
            size_t off = ((size_t)b*256 + mg)*HW + n0 + n;
            *(uint2*)(g_qh + off) = make_uint2((uint32_t)h0 | ((uint32_t)h1<<16),
                                               (uint32_t)h2 | ((uint32_t)h3<<16));
            *(uint2*)(g_ql + off) = make_uint2((uint32_t)l0 | ((uint32_t)l1<<16),
                                               (uint32_t)l2 | ((uint32_t)l3<<16));
        }
    }
}

// ---------------- adaptive pooling via per-channel integral image -----------------
// outputs bf16 hi/lo: key [c][112] (pads zero), valt [s][c] (pad rows zero)
__global__ void pool_kernel()
{
    extern __shared__ float P[];   // [128][129]
    const int b = blockIdx.z, c = blockIdx.y, which = blockIdx.x;
    const int t = threadIdx.x;     // 0..127
    const float* src = (which == 0 ? g_q : g_v) + ((size_t)b*256 + c)*HW;

    for (int i = 0; i < 128; i++) P[i*129 + t] = src[i*128 + t];
    __syncthreads();
    { float s = 0.f;
      for (int j = 0; j < 128; j++) { s += P[t*129 + j]; P[t*129 + j] = s; } }
    __syncthreads();
    { float s = 0.f;
      for (int i = 0; i < 128; i++) { s += P[i*129 + t]; P[i*129 + t] = s; } }
    __syncthreads();
    if (t < 112) {
        float avg = 0.f;
        if (t < 110) {
            int sidx = t, sc, idx;
            if      (sidx == 0) { sc = 1; idx = 0; }
            else if (sidx < 10) { sc = 3; idx = sidx - 1; }
            else if (sidx < 46) { sc = 6; idx = sidx - 10; }
            else                { sc = 8; idx = sidx - 46; }
            int i = idx / sc, j = idx % sc;
            int h0 = (i*128)/sc, h1 = ((i+1)*128 + sc - 1)/sc;
            int w0 = (j*128)/sc, w1 = ((j+1)*128 + sc - 1)/sc;
            float s11 =                      P[(h1-1)*129 + (w1-1)];
            float s01 = (h0 > 0)           ? P[(h0-1)*129 + (w1-1)] : 0.f;
            float s10 = (w0 > 0)           ? P[(h1-1)*129 + (w0-1)] : 0.f;
            float s00 = (h0 > 0 && w0 > 0) ? P[(h0-1)*129 + (w0-1)] : 0.f;
            avg = (s11 - s01 - s10 + s00) / (float)((h1 - h0)*(w1 - w0));
        }
        unsigned short hh, ll; bf16split(avg, hh, ll);
        if (which == 0) {
            size_t o = ((size_t)b*256 + c)*112 + t;
            g_keyh[o] = hh; g_keyl[o] = ll;
        } else {
            size_t o = ((size_t)b*112 + t)*256 + c;
            g_valth[o] = hh; g_valtl[o] = ll;
        }
    }
}

// ================= tensor-core attention ==========================================
// phase1: sim = q^T @ key (M=128 px, N=112->128pad, K=256), bf16 3-split HMMA
// softmax (fp32 smem), convert attn -> bf16 hi/lo
// phase2: ctx = attn @ valt (M=128, N=256 in 2 passes, K=112), bf16 3-split HMMA
// smem: sim fp32 [128][120] @0 (61440B) | Ah/Al [128][120]b16 @61440 (2x30720,
//       overlaps phase1 staging 2x17408) | valt staging 2x8704 @122880
__global__ __launch_bounds__(256, 1)
void attn_kernel()
{
    extern __shared__ char smraw[];
    char* base = (char*)(((uintptr_t)smraw + 1023) & ~(uintptr_t)1023);
    float*    sim = (float*)base;                  // [128][120]
    ushort_t* Ah  = (ushort_t*)(base + 61440);     // [128][120]
    ushort_t* Al  = (ushort_t*)(base + 92160);
    char*     st1 = base + 61440;                  // phase1 staging, 2 x 17408
    char*     st2 = base + 122880;                 // valt staging,   2 x 8704

    const int b   = blockIdx.y;
    const int n0  = blockIdx.x * 128;
    const int tid = threadIdx.x;
    const int wid = tid >> 5, lane = tid & 31;
    const int lr  = lane & 15, lh = lane >> 4;
    const int mb  = (wid & 3) * 32;      // warp m-block (both phases)
    const int nb  = (wid >> 2) * 64;     // warp n-block (both phases)

    const ushort_t* gqh = g_qh + ((size_t)b*256)*HW + n0;
    const ushort_t* gql = g_ql + ((size_t)b*256)*HW + n0;
    const ushort_t* gkh = g_keyh + (size_t)b*256*112;
    const ushort_t* gkl = g_keyl + (size_t)b*256*112;

    // zero key pad cols (bytes 224..255 of each row), both stages/comps: 256 x 8B
    {
        int i = tid;
        int stg  = i >> 7;
        int comp = (i >> 6) & 1;
        int row  = (i >> 2) & 15;
        int q8   = i & 3;
        *(uint2*)(st1 + stg*17408 + 8704 + comp*4352 + row*272 + 224 + q8*8)
            = make_uint2(0u, 0u);
    }
    __syncthreads();

    // ---- phase 1: sim = q^T @ key ----
    auto load_stage1 = [&](int c) {
        uint32_t sa = smem_u32(st1 + (c & 1) * 17408);
        const int c0 = c * 16;
#pragma unroll
        for (int u = 0; u < 4; u++) {
            int id = tid + 256*u;
            if (id < 512) {
                int comp = id >> 8, row = (id >> 4) & 15, c16 = id & 15;
                const ushort_t* src = (comp ? gql : gqh) + (size_t)(c0 + row)*HW + c16*8;
                cp16(sa + comp*4352 + row*272 + c16*16, src);
            } else if (id < 960) {
                int idx = id - 512;
                int comp = idx / 224;
                int rem  = idx - comp*224;
                int row  = rem / 14, c16 = rem - row*14;
                const ushort_t* src = (comp ? gkl : gkh) + (size_t)(c0 + row)*112 + c16*8;
                cp16(sa + 8704 + comp*4352 + row*272 + c16*16, src);
            }
        }
        cp_commit();
    };

    float acc[2][8][4];
#pragma unroll
    for (int i = 0; i < 2; i++)
#pragma unroll
        for (int j = 0; j < 8; j++)
#pragma unroll
            for (int r = 0; r < 4; r++) acc[i][j][r] = 0.f;

    load_stage1(0);
    for (int c = 0; c < 16; c++) {
        if (c + 1 < 16) { load_stage1(c + 1); cp_wait<1>(); }
        else            { cp_wait<0>(); }
        __syncthreads();
        uint32_t qa = smem_u32(st1 + (c & 1)*17408);
        uint32_t ka = qa + 8704;
        uint32_t ah[2][4], al[2][4], r4[4];
#pragma unroll
        for (int mi = 0; mi < 2; mi++) {
            uint32_t off = lr*272 + (mb + mi*16 + lh*8)*2;
            ldsm4t(r4, qa + off);
            ah[mi][0]=r4[0]; ah[mi][1]=r4[2]; ah[mi][2]=r4[1]; ah[mi][3]=r4[3];
            ldsm4t(r4, qa + 4352 + off);
            al[mi][0]=r4[0]; al[mi][1]=r4[2]; al[mi][2]=r4[1]; al[mi][3]=r4[3];
        }
        uint32_t bh[4][4], bl[4][4];
#pragma unroll
        for (int t = 0; t < 4; t++) {
            uint32_t off = lr*272 + (nb + t*16 + lh*8)*2;
            ldsm4t(bh[t], ka + off);
            ldsm4t(bl[t], ka + 4352 + off);
        }
#pragma unroll
        for (int mi = 0; mi < 2; mi++)
#pragma unroll
            for (int nj = 0; nj < 8; nj++) {
                int p = nj >> 1, q = (nj & 1)*2;
                mma16816(acc[mi][nj], ah[mi], bh[p][q], bh[p][q+1]);
            }
#pragma unroll
        for (int mi = 0; mi < 2; mi++)
#pragma unroll
            for (int nj = 0; nj < 8; nj++) {
                int p = nj >> 1, q = (nj & 1)*2;
                mma16816(acc[mi][nj], ah[mi], bl[p][q], bl[p][q+1]);
            }
#pragma unroll
        for (int mi = 0; mi < 2; mi++)
#pragma unroll
            for (int nj = 0; nj < 8; nj++) {
                int p = nj >> 1, q = (nj & 1)*2;
                mma16816(acc[mi][nj], al[mi], bh[p][q], bh[p][q+1]);
            }
        __syncthreads();
    }

    // frags -> sim fp32 (scaled by 256^-0.5)
#pragma unroll
    for (int mi = 0; mi < 2; mi++)
#pragma unroll
        for (int nj = 0; nj < 8; nj++) {
            int col = nb + nj*8 + (lane & 3)*2;
            if (col < 112) {
                int m = mb + mi*16 + (lane >> 2);
                sim[m*120 + col]       = acc[mi][nj][0] * 0.0625f;
                sim[m*120 + col + 1]   = acc[mi][nj][1] * 0.0625f;
                sim[(m+8)*120 + col]   = acc[mi][nj][2] * 0.0625f;
                sim[(m+8)*120 + col+1] = acc[mi][nj][3] * 0.0625f;
            }
        }
    __syncthreads();

    // softmax: 2 threads per row
    {
        int row = tid >> 1, half = tid & 1;
        float* r = sim + row*120;
        int s0 = half*55, s1 = s0 + 55;
        float mx = -1e30f;
        for (int s = s0; s < s1; s++) mx = fmaxf(mx, r[s]);
        mx = fmaxf(mx, __shfl_xor_sync(0xFFFFFFFFu, mx, 1));
        float sum = 0.f;
        for (int s = s0; s < s1; s++) { float e = __expf(r[s] - mx); r[s] = e; sum += e; }
        sum += __shfl_xor_sync(0xFFFFFFFFu, sum, 1);
        float inv = 1.f / sum;
        for (int s = s0; s < s1; s++) r[s] *= inv;
        if (half == 0) { r[110] = 0.f; r[111] = 0.f; }
    }
    __syncthreads();

    // convert attn -> bf16 hi/lo (overwrites phase1 staging region)
    {
        int row = tid >> 1, h0 = (tid & 1)*56;
        for (int s = h0; s < h0 + 56; s++) {
            unsigned short hh, ll;
            bf16split(sim[row*120 + s], hh, ll);
            Ah[row*120 + s] = hh;
            Al[row*120 + s] = ll;
        }
    }
    __syncthreads();

    // ---- phase 2: ctx = attn @ valt, two 128-channel passes ----
    const ushort_t* gvh = g_valth + (size_t)b*112*256;
    const ushort_t* gvl = g_valtl + (size_t)b*112*256;
    const uint32_t Aaddr = smem_u32(Ah);
    const size_t cbase = (size_t)b*256*HW + n0;

    for (int hp = 0; hp < 2; hp++) {
        auto load_stage2 = [&](int s) {
            uint32_t sa = smem_u32(st2 + (s & 1)*8704);
            const int s0 = s * 16;
#pragma unroll
            for (int u = 0; u < 2; u++) {
                int id = tid + 256*u;         // 0..511
                int comp = id >> 8, row = (id >> 4) & 15, c16 = id & 15;
                const ushort_t* src = (comp ? gvl : gvh)
                    + (size_t)(s0 + row)*256 + hp*128 + c16*8;
                cp16(sa + comp*4352 + row*272 + c16*16, src);
            }
            cp_commit();
        };

        float acc2[2][8][4];
#pragma unroll
        for (int i = 0; i < 2; i++)
#pragma unroll
            for (int j = 0; j < 8; j++)
#pragma unroll
                for (int r = 0; r < 4; r++) acc2[i][j][r] = 0.f;

        load_stage2(0);
        for (int s = 0; s < 7; s++) {
            if (s + 1 < 7) { load_stage2(s + 1); cp_wait<1>(); }
            else           { cp_wait<0>(); }
            __syncthreads();
            uint32_t va = smem_u32(st2 + (s & 1)*8704);
            uint32_t ah2[2][4], al2[2][4];
#pragma unroll
            for (int mi = 0; mi < 2; mi++) {
                uint32_t off = (uint32_t)((mb + mi*16 + lr)*240 + (s*16 + lh*8)*2);
                ldsm4(ah2[mi], Aaddr + off);
                ldsm4(al2[mi], Aaddr + 30720 + off);
            }
            uint32_t bh2[4][4], bl2[4][4];
#pragma unroll
            for (int t = 0; t < 4; t++) {
                uint32_t off = lr*272 + (nb + t*16 + lh*8)*2;
                ldsm4t(bh2[t], va + off);
                ldsm4t(bl2[t], va + 4352 + off);
            }
#pragma unroll
            for (int mi = 0; mi < 2; mi++)
#pragma unroll
                for (int nj = 0; nj < 8; nj++) {
                    int p = nj >> 1, q = (nj & 1)*2;
                    mma16816(acc2[mi][nj], ah2[mi], bh2[p][q], bh2[p][q+1]);
                }
#pragma unroll
            for (int mi = 0; mi < 2; mi++)
#pragma unroll
                for (int nj = 0; nj < 8; nj++) {
                    int p = nj >> 1, q = (nj & 1)*2;
                    mma16816(acc2[mi][nj], ah2[mi], bl2[p][q], bl2[p][q+1]);
                }
#pragma unroll
            for (int mi = 0; mi < 2; mi++)
#pragma unroll
                for (int nj = 0; nj < 8; nj++) {
                    int p = nj >> 1, q = (nj & 1)*2;
                    mma16816(acc2[mi][nj], al2[mi], bh2[p][q], bh2[p][q+1]);
                }
            __syncthreads();
        }

        // write ctx bf16 hi/lo (channel-major)
#pragma unroll
        for (int mi = 0; mi < 2; mi++)
#pragma unroll
            for (int nj = 0; nj < 8; nj++) {
                int m = mb + mi*16 + (lane >> 2);
                int cch = hp*128 + nb + nj*8 + (lane & 3)*2;
                unsigned short hh, ll;
#pragma unroll
                for (int r = 0; r < 4; r++) {
                    int mm = m + (r >> 1)*8;
                    int cc = cch + (r & 1);
                    bf16split(acc2[mi][nj][r], hh, ll);
                    size_t o = cbase + (size_t)cc*HW + mm;
                    g_ctxh[o] = hh;
                    g_ctxl[o] = ll;
                }
            }
    }
}

// ----------------------------------------------------------------------------------
extern "C" void kernel_launch(void* const* d_in, const int* in_sizes, int n_in,
                              void* d_out, int out_size)
{
    const float* feats = (const float*)d_in[0];
    const float* w_kq  = (const float*)d_in[1];
    const float* b_kq  = (const float*)d_in[2];
    const float* w_v   = (const float*)d_in[3];
    const float* b_v   = (const float*)d_in[4];
    const float* w_out = (const float*)d_in[5];
    const float* b_out = (const float*)d_in[6];
    const float* w_bot = (const float*)d_in[7];
    const float* b_bot = (const float*)d_in[8];
    float* out = (float*)d_out;

    const int pool_smem = 128*129*4;                 // 66048
    const int attn_smem = 157696 + 1024;             // 158720
    const int mma_smem  = 2*STAGE + 1024;            // 201728
    cudaFuncSetAttribute(pool_kernel, cudaFuncAttributeMaxDynamicSharedMemorySize, pool_smem);
    cudaFuncSetAttribute(attn_kernel, cudaFuncAttributeMaxDynamicSharedMemorySize, attn_smem);
    cudaFuncSetAttribute(mma_gemm_kernel<0>, cudaFuncAttributeMaxDynamicSharedMemorySize, mma_smem);
    cudaFuncSetAttribute(mma_gemm_kernel<1>, cudaFuncAttributeMaxDynamicSharedMemorySize, mma_smem);

    weff_kernel<<<512, 256>>>(w_out, b_out, w_bot, b_bot);
    splitA0_kernel<<<512, 256>>>(w_kq, w_v);
    splitA1_kernel<<<512, 256>>>(w_bot);
    split_feats_kernel<<<4096, 256>>>(feats);
    mma_gemm_kernel<0><<<dim3(4, 64, BATCH), 512, mma_smem>>>(b_kq, b_v, out);
    pool_kernel<<<dim3(2, 256, BATCH), 128, pool_smem>>>();
    attn_kernel<<<dim3(128, BATCH), 256, attn_smem>>>();
    mma_gemm_kernel<1><<<dim3(4, 64, BATCH), 512, mma_smem>>>(b_kq, b_v, out);
}

// round 15
// speedup vs baseline: 2.4475x; 1.1355x over previous
#include <cuda_runtime.h>
#include <cuda.h>
#include <cuda_bf16.h>
#include <cstddef>
#include <cstdint>

#define BATCH 4
#define HW 16384   // 128*128

typedef unsigned short ushort_t;

// ---------------- scratch (device globals; no allocation allowed) ----------------
__device__ float    g_q   [(size_t)BATCH*256*HW];   // q fp32 (pool input)
__device__ float    g_v   [(size_t)BATCH*256*HW];   // v fp32 (pool input)
__device__ ushort_t g_qh  [(size_t)BATCH*256*HW];   // q bf16 hi (attn input)
__device__ ushort_t g_ql  [(size_t)BATCH*256*HW];   // q bf16 lo
__device__ ushort_t g_ctxh[(size_t)BATCH*256*HW];   // ctx bf16 hi
__device__ ushort_t g_ctxl[(size_t)BATCH*256*HW];   // ctx bf16 lo
__device__ ushort_t g_fh  [(size_t)BATCH*512*HW];   // feats bf16 hi
__device__ ushort_t g_fl  [(size_t)BATCH*512*HW];   // feats bf16 lo
__device__ ushort_t g_keyh[(size_t)BATCH*256*112];  // pooled q bf16 hi [c][112]
__device__ ushort_t g_keyl[(size_t)BATCH*256*112];
__device__ ushort_t g_valth[(size_t)BATCH*112*256]; // pooled v bf16 hi [s][c]
__device__ ushort_t g_valtl[(size_t)BATCH*112*256];
__device__ float    g_weff[512*256];
__device__ float    g_beff[512];
__device__ ushort_t g_A0h[512*512], g_A0l[512*512];     // [w_kq; w_v] hi/lo
__device__ ushort_t g_A1h[512*768], g_A1l[512*768];     // [Weff | Wbot_right] hi/lo

// ============================ helpers ===============================
__device__ __forceinline__ uint32_t smem_u32(const void* p) {
    uint32_t a;
    asm("{ .reg .u64 t; cvta.to.shared.u64 t, %1; cvt.u32.u64 %0, t; }" : "=r"(a) : "l"(p));
    return a;
}
__device__ __forceinline__ uint32_t swz(uint32_t o) { return o ^ ((o >> 3) & 0x70); }

__device__ __forceinline__ void ldsm4(uint32_t* r, uint32_t addr) {
    asm volatile("ldmatrix.sync.aligned.m8n8.x4.shared.b16 {%0,%1,%2,%3}, [%4];"
                 : "=r"(r[0]), "=r"(r[1]), "=r"(r[2]), "=r"(r[3]) : "r"(addr));
}
__device__ __forceinline__ void ldsm4t(uint32_t* r, uint32_t addr) {
    asm volatile("ldmatrix.sync.aligned.m8n8.x4.trans.shared.b16 {%0,%1,%2,%3}, [%4];"
                 : "=r"(r[0]), "=r"(r[1]), "=r"(r[2]), "=r"(r[3]) : "r"(addr));
}
__device__ __forceinline__ void mma16816(float* c, const uint32_t* a, uint32_t b0, uint32_t b1) {
    asm volatile(
        "mma.sync.aligned.m16n8k16.row.col.f32.bf16.bf16.f32 "
        "{%0,%1,%2,%3}, {%4,%5,%6,%7}, {%8,%9}, {%0,%1,%2,%3};"
        : "+f"(c[0]), "+f"(c[1]), "+f"(c[2]), "+f"(c[3])
        : "r"(a[0]), "r"(a[1]), "r"(a[2]), "r"(a[3]), "r"(b0), "r"(b1));
}
__device__ __forceinline__ void bf16split(float x, unsigned short& h, unsigned short& l) {
    __nv_bfloat16 hb = __float2bfloat16_rn(x);
    float r = x - __bfloat162float(hb);
    __nv_bfloat16 lb = __float2bfloat16_rn(r);
    h = __bfloat16_as_ushort(hb);
    l = __bfloat16_as_ushort(lb);
}
__device__ __forceinline__ void cp16(uint32_t s, const void* g) {
    asm volatile("cp.async.cg.shared.global [%0], [%1], 16;"
                 :: "r"(s), "l"(__cvta_generic_to_global(g)) : "memory");
}
__device__ __forceinline__ void cp_commit() {
    asm volatile("cp.async.commit_group;" ::: "memory");
}
template<int N>
__device__ __forceinline__ void cp_wait() {
    asm volatile("cp.async.wait_group %0;" :: "n"(N) : "memory");
}
// -------- TMA + mbarrier (sm_90 base features) --------
__device__ __forceinline__ void tma2d(uint32_t smem, const CUtensorMap* m, int x, int y, uint32_t mb) {
    asm volatile("cp.async.bulk.tensor.2d.shared::cta.global.tile.mbarrier::complete_tx::bytes "
                 "[%0], [%1, {%2, %3}], [%4];"
                 :: "r"(smem), "l"(m), "r"(x), "r"(y), "r"(mb) : "memory");
}
__device__ __forceinline__ void mbar_init(uint32_t a, uint32_t cnt) {
    asm volatile("mbarrier.init.shared.b64 [%0], %1;" :: "r"(a), "r"(cnt) : "memory");
}
__device__ __forceinline__ void mbar_expect_tx(uint32_t a, uint32_t bytes) {
    asm volatile("mbarrier.arrive.expect_tx.shared.b64 _, [%0], %1;" :: "r"(a), "r"(bytes) : "memory");
}
__device__ __forceinline__ void mbar_wait(uint32_t a, uint32_t parity) {
    asm volatile(
        "{\n\t.reg .pred P;\n\t"
        "LAB%=: mbarrier.try_wait.parity.acquire.cta.shared::cta.b64 P, [%0], %1, 0x989680;\n\t"
        "@!P bra LAB%=;\n\t}"
        :: "r"(a), "r"(parity) : "memory");
}
__device__ __forceinline__ void fence_proxy_async_cta() {
    asm volatile("fence.proxy.async.shared::cta;" ::: "memory");
}

// ---------------- W_eff = W_bot[:, :512] @ W_out ; b_eff = W_bot[:,:512]@b_out + b_bot
__global__ void weff_kernel(const float* __restrict__ w_out, const float* __restrict__ b_out,
                            const float* __restrict__ w_bot, const float* __restrict__ b_bot)
{
    int m = blockIdx.x;      // 0..511
    int k = threadIdx.x;     // 0..255
    float a0 = 0.f, a1 = 0.f, a2 = 0.f, a3 = 0.f;
    for (int j = 0; j < 512; j += 4) {
        a0 += w_bot[m*1024 + j + 0] * w_out[(j + 0)*256 + k];
        a1 += w_bot[m*1024 + j + 1] * w_out[(j + 1)*256 + k];
        a2 += w_bot[m*1024 + j + 2] * w_out[(j + 2)*256 + k];
        a3 += w_bot[m*1024 + j + 3] * w_out[(j + 3)*256 + k];
    }
    g_weff[m*256 + k] = (a0 + a1) + (a2 + a3);
    if (k == 0) {
        float bb = b_bot[m];
        for (int j = 0; j < 512; j++) bb += w_bot[m*1024 + j] * b_out[j];
        g_beff[m] = bb;
    }
}

// ---------------- operand pre-split kernels (fp32 -> bf16 hi/lo) ------------------
__global__ void splitA0_kernel(const float* __restrict__ w_kq, const float* __restrict__ w_v)
{
    int m = blockIdx.x;
    for (int k = threadIdx.x; k < 512; k += 256) {
        float v = (m < 256) ? w_kq[m*512 + k] : w_v[(m - 256)*512 + k];
        unsigned short h, l; bf16split(v, h, l);
        g_A0h[m*512 + k] = h; g_A0l[m*512 + k] = l;
    }
}
__global__ void splitA1_kernel(const float* __restrict__ w_bot)
{
    int m = blockIdx.x;
    for (int k = threadIdx.x; k < 768; k += 256) {
        float v = (k < 256) ? g_weff[m*256 + k] : w_bot[m*1024 + 256 + k];
        unsigned short h, l; bf16split(v, h, l);
        g_A1h[m*768 + k] = h; g_A1l[m*768 + k] = l;
    }
}
__global__ void split_feats_kernel(const float* __restrict__ f)
{
    const size_t N4 = (size_t)BATCH*512*HW/4;
    for (size_t t = (size_t)blockIdx.x*blockDim.x + threadIdx.x;
         t < N4; t += (size_t)gridDim.x*blockDim.x) {
        float4 v = ((const float4*)f)[t];
        unsigned short h0,h1,h2,h3,l0,l1,l2,l3;
        bf16split(v.x,h0,l0); bf16split(v.y,h1,l1);
        bf16split(v.z,h2,l2); bf16split(v.w,h3,l3);
        ((uint2*)g_fh)[t] = make_uint2((uint32_t)h0 | ((uint32_t)h1<<16),
                                       (uint32_t)h2 | ((uint32_t)h3<<16));
        ((uint2*)g_fl)[t] = make_uint2((uint32_t)l0 | ((uint32_t)l1<<16),
                                       (uint32_t)l2 | ((uint32_t)l3<<16));
    }
}

// ================= TMA-fed mma.sync bf16 3-split GEMM =============================
// CTA tile 128m x 256n, 16 warps (each 64m x 32n), BK=64, 2-stage TMA pipeline.
// Stage layout: A hi 16384 | A lo 16384 | B hi 4x8192 | B lo 4x8192 = 98304 B.
// All tiles SW128-swizzled 128B rows (matches swz()).
#define A_BYTES 16384
#define STAGE_B 98304
#define CHUNK_TX 98304u

template<int MODE>
__global__ __launch_bounds__(512, 1)
void mma_gemm_kernel(const __grid_constant__ CUtensorMap tmAh,
                     const __grid_constant__ CUtensorMap tmAl,
                     const __grid_constant__ CUtensorMap tmBh,
                     const __grid_constant__ CUtensorMap tmBl,
                     const __grid_constant__ CUtensorMap tmB2h,
                     const __grid_constant__ CUtensorMap tmB2l,
                     const float* __restrict__ b_kq, const float* __restrict__ b_v,
                     float* __restrict__ out)
{
    constexpr int K  = (MODE == 0) ? 512 : 768;
    constexpr int NC = K / 64;
    extern __shared__ char dyn[];
    char* base = (char*)(((uintptr_t)dyn + 1023) & ~(uintptr_t)1023);
    __shared__ alignas(8) unsigned long long s_mbar[2];

    const int tid  = threadIdx.x;
    const int wid  = tid >> 5, lane = tid & 31;
    const int wm   = wid & 1,  wn   = wid >> 1;       // wn 0..7
    const int m0   = blockIdx.x * 128;                // x = m-tile (L2 reuse of B)
    const int n0   = blockIdx.y * 256;
    const int b    = blockIdx.z;
    const int lr   = lane & 15, lh = lane >> 4;

    if (tid == 0) { mbar_init(smem_u32(&s_mbar[0]), 1); mbar_init(smem_u32(&s_mbar[1]), 1); }
    __syncthreads();
    if (tid == 0) fence_proxy_async_cta();
    __syncthreads();

    float acc[4][4][4];
#pragma unroll
    for (int i = 0; i < 4; i++)
#pragma unroll
        for (int j = 0; j < 4; j++)
#pragma unroll
            for (int r = 0; r < 4; r++) acc[i][j][r] = 0.f;

    auto issue_chunk = [&](int c) {
        // caller guarantees tid==0
        const int buf = c & 1;
        const int k0  = c * 64;
        uint32_t sa = smem_u32(base + buf * STAGE_B);
        uint32_t mb = smem_u32(&s_mbar[buf]);
        mbar_expect_tx(mb, CHUNK_TX);
        tma2d(sa,           &tmAh, k0, m0, mb);
        tma2d(sa + A_BYTES, &tmAl, k0, m0, mb);
        const CUtensorMap *bh, *bl; int y;
        if (MODE == 0)     { bh = &tmBh;  bl = &tmBl;  y = b*512 + k0; }
        else if (k0 < 256) { bh = &tmBh;  bl = &tmBl;  y = b*256 + k0; }        // ctx
        else               { bh = &tmB2h; bl = &tmB2l; y = b*512 + (k0 - 256); } // feats
#pragma unroll
        for (int s = 0; s < 4; s++) {
            tma2d(sa + 2*A_BYTES + s*8192,         bh, n0 + 64*s, y, mb);
            tma2d(sa + 2*A_BYTES + 32768 + s*8192, bl, n0 + 64*s, y, mb);
        }
    };

    auto compute = [&](int c) {
        uint32_t aH = smem_u32(base + (c & 1) * STAGE_B);
        uint32_t aL = aH + A_BYTES;
        uint32_t bH = aL + A_BYTES;
        uint32_t bL = bH + 32768;
#pragma unroll
        for (int kk = 0; kk < 4; kk++) {
            const int k0 = kk * 16;
            uint32_t ah[4][4], al[4][4];
#pragma unroll
            for (int mi = 0; mi < 4; mi++) {
                int row = wm*64 + mi*16 + lr;
                uint32_t off = swz((uint32_t)(row*128 + (k0 + lh*8)*2));
                ldsm4(ah[mi], aH + off);
                ldsm4(al[mi], aL + off);
            }
            uint32_t bh[2][4], bl[2][4];
#pragma unroll
            for (int p = 0; p < 2; p++) {
                int n = wn*32 + p*16 + lh*8;
                uint32_t off = (uint32_t)((n >> 6) * 8192)
                             + swz((uint32_t)((k0 + lr)*128 + (n & 63)*2));
                ldsm4t(bh[p], bH + off);
                ldsm4t(bl[p], bL + off);
            }
#pragma unroll
            for (int mi = 0; mi < 4; mi++)
#pragma unroll
                for (int nj = 0; nj < 4; nj++) {
                    int p = nj >> 1, q = (nj & 1) * 2;
                    mma16816(acc[mi][nj], ah[mi], bh[p][q], bh[p][q+1]);
                }
#pragma unroll
            for (int mi = 0; mi < 4; mi++)
#pragma unroll
                for (int nj = 0; nj < 4; nj++) {
                    int p = nj >> 1, q = (nj & 1) * 2;
                    mma16816(acc[mi][nj], ah[mi], bl[p][q], bl[p][q+1]);
                }
#pragma unroll
            for (int mi = 0; mi < 4; mi++)
#pragma unroll
                for (int nj = 0; nj < 4; nj++) {
                    int p = nj >> 1, q = (nj & 1) * 2;
                    mma16816(acc[mi][nj], al[mi], bh[p][q], bh[p][q+1]);
                }
        }
    };

    if (tid == 0) { issue_chunk(0); issue_chunk(1); }
    for (int c = 0; c < NC; c++) {
        mbar_wait(smem_u32(&s_mbar[c & 1]), (uint32_t)((c >> 1) & 1));
        compute(c);
        __syncthreads();
        if (tid == 0 && c + 2 < NC) issue_chunk(c + 2);
    }

    // ---- epilogue: frags -> smem [128][260] -> coalesced gmem + bias/relu ----
    float* sD = (float*)base;
    {
        int tq = lane & 3, tr = lane >> 2;
#pragma unroll
        for (int mi = 0; mi < 4; mi++)
#pragma unroll
            for (int nj = 0; nj < 4; nj++) {
                int r0 = wm*64 + mi*16 + tr;
                int cc = wn*32 + nj*8 + tq*2;
                *(float2*)&sD[(size_t)r0*260 + cc]     = make_float2(acc[mi][nj][0], acc[mi][nj][1]);
                *(float2*)&sD[(size_t)(r0+8)*260 + cc] = make_float2(acc[mi][nj][2], acc[mi][nj][3]);
            }
    }
    __syncthreads();
#pragma unroll
    for (int u = 0; u < 16; u++) {
        int idx4 = tid + 512 * u;            // 0..8191
        int m = idx4 >> 6;                   // 0..127
        int n = (idx4 & 63) * 4;             // 0..252
        int mg = m0 + m;
        float bias; float* dst; bool rl; bool isq = false;
        if (MODE == 0) {
            isq = (mg < 256);
            bias = isq ? b_kq[mg] : b_v[mg - 256];
            dst  = isq ? (g_q + ((size_t)b*256 + mg) * HW)
                       : (g_v + ((size_t)b*256 + (mg-256)) * HW);
            rl = isq;
        } else {
            bias = g_beff[mg];
            dst  = out + ((size_t)b*512 + mg) * HW;
            rl = true;
        }
        float4 o;
        o.x = sD[(size_t)m*260 + n + 0] + bias;
        o.y = sD[(size_t)m*260 + n + 1] + bias;
        o.z = sD[(size_t)m*260 + n + 2] + bias;
        o.w = sD[(size_t)m*260 + n + 3] + bias;
        if (rl) {
            o.x = fmaxf(o.x, 0.f); o.y = fmaxf(o.y, 0.f);
            o.z = fmaxf(o.z, 0.f); o.w = fmaxf(o.w, 0.f);
        }
        *(float4*)(dst + n0 + n) = o;
        if (MODE == 0 && isq) {
            unsigned short h0,l0,h1,l1,h2,l2,h3,l3;
            bf16split(o.x,h0,l0); bf16split(o.y,h1,l1);
            bf16split(o.z,h2,l2); bf16split(o.w,h3,l3);
            size_t off = ((size_t)b*256 + mg)*HW + n0 + n;
            *(uint2*)(g_qh + off) = make_uint2((uint32_t)h0 | ((uint32_t)h1<<16),
                                               (uint32_t)h2 | ((uint32_t)h3<<16));
            *(uint2*)(g_ql + off) = make_uint2((uint32_t)l0 | ((uint32_t)l1<<16),
                                               (uint32_t)l2 | ((uint32_t)l3<<16));
        }
    }
}

// ---------------- adaptive pooling via per-channel integral image -----------------
__global__ void pool_kernel()
{
    extern __shared__ float P[];   // [128][129]
    const int b = blockIdx.z, c = blockIdx.y, which = blockIdx.x;
    const int t = threadIdx.x;     // 0..127
    const float* src = (which == 0 ? g_q : g_v) + ((size_t)b*256 + c)*HW;

    for (int i = 0; i < 128; i++) P[i*129 + t] = src[i*128 + t];
    __syncthreads();
    { float s = 0.f;
      for (int j = 0; j < 128; j++) { s += P[t*129 + j]; P[t*129 + j] = s; } }
    __syncthreads();
    { float s = 0.f;
      for (int i = 0; i < 128; i++) { s += P[i*129 + t]; P[i*129 + t] = s; } }
    __syncthreads();
    if (t < 112) {
        float avg = 0.f;
        if (t < 110) {
            int sidx = t, sc, idx;
            if      (sidx == 0) { sc = 1; idx = 0; }
            else if (sidx < 10) { sc = 3; idx = sidx - 1; }
            else if (sidx < 46) { sc = 6; idx = sidx - 10; }
            else                { sc = 8; idx = sidx - 46; }
            int i = idx / sc, j = idx % sc;
            int h0 = (i*128)/sc, h1 = ((i+1)*128 + sc - 1)/sc;
            int w0 = (j*128)/sc, w1 = ((j+1)*128 + sc - 1)/sc;
            float s11 =                      P[(h1-1)*129 + (w1-1)];
            float s01 = (h0 > 0)           ? P[(h0-1)*129 + (w1-1)] : 0.f;
            float s10 = (w0 > 0)           ? P[(h1-1)*129 + (w0-1)] : 0.f;
            float s00 = (h0 > 0 && w0 > 0) ? P[(h0-1)*129 + (w0-1)] : 0.f;
            avg = (s11 - s01 - s10 + s00) / (float)((h1 - h0)*(w1 - w0));
        }
        unsigned short hh, ll; bf16split(avg, hh, ll);
        if (which == 0) {
            size_t o = ((size_t)b*256 + c)*112 + t;
            g_keyh[o] = hh; g_keyl[o] = ll;
        } else {
            size_t o = ((size_t)b*112 + t)*256 + c;
            g_valth[o] = hh; g_valtl[o] = ll;
        }
    }
}

// ================= tensor-core attention (unchanged from round 14) ================
__global__ __launch_bounds__(256, 1)
void attn_kernel()
{
    extern __shared__ char smraw[];
    char* base = (char*)(((uintptr_t)smraw + 1023) & ~(uintptr_t)1023);
    float*    sim = (float*)base;                  // [128][120]
    ushort_t* Ah  = (ushort_t*)(base + 61440);     // [128][120]
    ushort_t* Al  = (ushort_t*)(base + 92160);
    char*     st1 = base + 61440;                  // phase1 staging, 2 x 17408
    char*     st2 = base + 122880;                 // valt staging,   2 x 8704

    const int b   = blockIdx.y;
    const int n0  = blockIdx.x * 128;
    const int tid = threadIdx.x;
    const int wid = tid >> 5, lane = tid & 31;
    const int lr  = lane & 15, lh = lane >> 4;
    const int mb  = (wid & 3) * 32;
    const int nb  = (wid >> 2) * 64;

    const ushort_t* gqh = g_qh + ((size_t)b*256)*HW + n0;
    const ushort_t* gql = g_ql + ((size_t)b*256)*HW + n0;
    const ushort_t* gkh = g_keyh + (size_t)b*256*112;
    const ushort_t* gkl = g_keyl + (size_t)b*256*112;

    {
        int i = tid;
        int stg  = i >> 7;
        int comp = (i >> 6) & 1;
        int row  = (i >> 2) & 15;
        int q8   = i & 3;
        *(uint2*)(st1 + stg*17408 + 8704 + comp*4352 + row*272 + 224 + q8*8)
            = make_uint2(0u, 0u);
    }
    __syncthreads();

    auto load_stage1 = [&](int c) {
        uint32_t sa = smem_u32(st1 + (c & 1) * 17408);
        const int c0 = c * 16;
#pragma unroll
        for (int u = 0; u < 4; u++) {
            int id = tid + 256*u;
            if (id < 512) {
                int comp = id >> 8, row = (id >> 4) & 15, c16 = id & 15;
                const ushort_t* src = (comp ? gql : gqh) + (size_t)(c0 + row)*HW + c16*8;
                cp16(sa + comp*4352 + row*272 + c16*16, src);
            } else if (id < 960) {
                int idx = id - 512;
                int comp = idx / 224;
                int rem  = idx - comp*224;
                int row  = rem / 14, c16 = rem - row*14;
                const ushort_t* src = (comp ? gkl : gkh) + (size_t)(c0 + row)*112 + c16*8;
                cp16(sa + 8704 + comp*4352 + row*272 + c16*16, src);
            }
        }
        cp_commit();
    };

    float acc[2][8][4];
#pragma unroll
    for (int i = 0; i < 2; i++)
#pragma unroll
        for (int j = 0; j < 8; j++)
#pragma unroll
            for (int r = 0; r < 4; r++) acc[i][j][r] = 0.f;

    load_stage1(0);
    for (int c = 0; c < 16; c++) {
        if (c + 1 < 16) { load_stage1(c + 1); cp_wait<1>(); }
        else            { cp_wait<0>(); }
        __syncthreads();
        uint32_t qa = smem_u32(st1 + (c & 1)*17408);
        uint32_t ka = qa + 8704;
        uint32_t ah[2][4], al[2][4], r4[4];
#pragma unroll
        for (int mi = 0; mi < 2; mi++) {
            uint32_t off = lr*272 + (mb + mi*16 + lh*8)*2;
            ldsm4t(r4, qa + off);
            ah[mi][0]=r4[0]; ah[mi][1]=r4[2]; ah[mi][2]=r4[1]; ah[mi][3]=r4[3];
            ldsm4t(r4, qa + 4352 + off);
            al[mi][0]=r4[0]; al[mi][1]=r4[2]; al[mi][2]=r4[1]; al[mi][3]=r4[3];
        }
        uint32_t bh[4][4], bl[4][4];
#pragma unroll
        for (int t = 0; t < 4; t++) {
            uint32_t off = lr*272 + (nb + t*16 + lh*8)*2;
            ldsm4t(bh[t], ka + off);
            ldsm4t(bl[t], ka + 4352 + off);
        }
#pragma unroll
        for (int mi = 0; mi < 2; mi++)
#pragma unroll
            for (int nj = 0; nj < 8; nj++) {
                int p = nj >> 1, q = (nj & 1)*2;
                mma16816(acc[mi][nj], ah[mi], bh[p][q], bh[p][q+1]);
            }
#pragma unroll
        for (int mi = 0; mi < 2; mi++)
#pragma unroll
            for (int nj = 0; nj < 8; nj++) {
                int p = nj >> 1, q = (nj & 1)*2;
                mma16816(acc[mi][nj], ah[mi], bl[p][q], bl[p][q+1]);
            }
#pragma unroll
        for (int mi = 0; mi < 2; mi++)
#pragma unroll
            for (int nj = 0; nj < 8; nj++) {
                int p = nj >> 1, q = (nj & 1)*2;
                mma16816(acc[mi][nj], al[mi], bh[p][q], bh[p][q+1]);
            }
        __syncthreads();
    }

#pragma unroll
    for (int mi = 0; mi < 2; mi++)
#pragma unroll
        for (int nj = 0; nj < 8; nj++) {
            int col = nb + nj*8 + (lane & 3)*2;
            if (col < 112) {
                int m = mb + mi*16 + (lane >> 2);
                sim[m*120 + col]       = acc[mi][nj][0] * 0.0625f;
                sim[m*120 + col + 1]   = acc[mi][nj][1] * 0.0625f;
                sim[(m+8)*120 + col]   = acc[mi][nj][2] * 0.0625f;
                sim[(m+8)*120 + col+1] = acc[mi][nj][3] * 0.0625f;
            }
        }
    __syncthreads();

    {
        int row = tid >> 1, half = tid & 1;
        float* r = sim + row*120;
        int s0 = half*55, s1 = s0 + 55;
        float mx = -1e30f;
        for (int s = s0; s < s1; s++) mx = fmaxf(mx, r[s]);
        mx = fmaxf(mx, __shfl_xor_sync(0xFFFFFFFFu, mx, 1));
        float sum = 0.f;
        for (int s = s0; s < s1; s++) { float e = __expf(r[s] - mx); r[s] = e; sum += e; }
        sum += __shfl_xor_sync(0xFFFFFFFFu, sum, 1);
        float inv = 1.f / sum;
        for (int s = s0; s < s1; s++) r[s] *= inv;
        if (half == 0) { r[110] = 0.f; r[111] = 0.f; }
    }
    __syncthreads();

    {
        int row = tid >> 1, h0 = (tid & 1)*56;
        for (int s = h0; s < h0 + 56; s++) {
            unsigned short hh, ll;
            bf16split(sim[row*120 + s], hh, ll);
            Ah[row*120 + s] = hh;
            Al[row*120 + s] = ll;
        }
    }
    __syncthreads();

    const ushort_t* gvh = g_valth + (size_t)b*112*256;
    const ushort_t* gvl = g_valtl + (size_t)b*112*256;
    const uint32_t Aaddr = smem_u32(Ah);
    const size_t cbase = (size_t)b*256*HW + n0;

    for (int hp = 0; hp < 2; hp++) {
        auto load_stage2 = [&](int s) {
            uint32_t sa = smem_u32(st2 + (s & 1)*8704);
            const int s0 = s * 16;
#pragma unroll
            for (int u = 0; u < 2; u++) {
                int id = tid + 256*u;         // 0..511
                int comp = id >> 8, row = (id >> 4) & 15, c16 = id & 15;
                const ushort_t* src = (comp ? gvl : gvh)
                    + (size_t)(s0 + row)*256 + hp*128 + c16*8;
                cp16(sa + comp*4352 + row*272 + c16*16, src);
            }
            cp_commit();
        };

        float acc2[2][8][4];
#pragma unroll
        for (int i = 0; i < 2; i++)
#pragma unroll
            for (int j = 0; j < 8; j++)
#pragma unroll
                for (int r = 0; r < 4; r++) acc2[i][j][r] = 0.f;

        load_stage2(0);
        for (int s = 0; s < 7; s++) {
            if (s + 1 < 7) { load_stage2(s + 1); cp_wait<1>(); }
            else           { cp_wait<0>(); }
            __syncthreads();
            uint32_t va = smem_u32(st2 + (s & 1)*8704);
            uint32_t ah2[2][4], al2[2][4];
#pragma unroll
            for (int mi = 0; mi < 2; mi++) {
                uint32_t off = (uint32_t)((mb + mi*16 + lr)*240 + (s*16 + lh*8)*2);
                ldsm4(ah2[mi], Aaddr + off);
                ldsm4(al2[mi], Aaddr + 30720 + off);
            }
            uint32_t bh2[4][4], bl2[4][4];
#pragma unroll
            for (int t = 0; t < 4; t++) {
                uint32_t off = lr*272 + (nb + t*16 + lh*8)*2;
                ldsm4t(bh2[t], va + off);
                ldsm4t(bl2[t], va + 4352 + off);
            }
#pragma unroll
            for (int mi = 0; mi < 2; mi++)
#pragma unroll
                for (int nj = 0; nj < 8; nj++) {
                    int p = nj >> 1, q = (nj & 1)*2;
                    mma16816(acc2[mi][nj], ah2[mi], bh2[p][q], bh2[p][q+1]);
                }
#pragma unroll
            for (int mi = 0; mi < 2; mi++)
#pragma unroll
                for (int nj = 0; nj < 8; nj++) {
                    int p = nj >> 1, q = (nj & 1)*2;
                    mma16816(acc2[mi][nj], ah2[mi], bl2[p][q], bl2[p][q+1]);
                }
#pragma unroll
            for (int mi = 0; mi < 2; mi++)
#pragma unroll
                for (int nj = 0; nj < 8; nj++) {
                    int p = nj >> 1, q = (nj & 1)*2;
                    mma16816(acc2[mi][nj], al2[mi], bh2[p][q], bh2[p][q+1]);
                }
            __syncthreads();
        }

#pragma unroll
        for (int mi = 0; mi < 2; mi++)
#pragma unroll
            for (int nj = 0; nj < 8; nj++) {
                int m = mb + mi*16 + (lane >> 2);
                int cch = hp*128 + nb + nj*8 + (lane & 3)*2;
                unsigned short hh, ll;
#pragma unroll
                for (int r = 0; r < 4; r++) {
                    int mm = m + (r >> 1)*8;
                    int cc = cch + (r & 1);
                    bf16split(acc2[mi][nj][r], hh, ll);
                    size_t o = cbase + (size_t)cc*HW + mm;
                    g_ctxh[o] = hh;
                    g_ctxl[o] = ll;
                }
            }
    }
}

// ------------------------- host-side TMA descriptor setup -------------------------
typedef CUresult (*PFN_encodeTiled)(
    CUtensorMap*, CUtensorMapDataType, unsigned int, void*,
    const unsigned long long*, const unsigned long long*,
    const unsigned int*, const unsigned int*,
    CUtensorMapInterleave, CUtensorMapSwizzle, CUtensorMapL2promotion,
    CUtensorMapFloatOOBfill);

static void enc2d(PFN_encodeTiled f, CUtensorMap* m, void* p,
                  unsigned long long rows, unsigned long long cols,
                  unsigned int box_inner, unsigned int box_rows)
{
    unsigned long long dims[2]    = {cols, rows};
    unsigned long long strides[1] = {cols * 2ull};     // u16
    unsigned int box[2]  = {box_inner, box_rows};
    unsigned int es[2]   = {1, 1};
    f(m, CU_TENSOR_MAP_DATA_TYPE_UINT16, 2, p, dims, strides, box, es,
      CU_TENSOR_MAP_INTERLEAVE_NONE, CU_TENSOR_MAP_SWIZZLE_128B,
      CU_TENSOR_MAP_L2_PROMOTION_L2_128B, CU_TENSOR_MAP_FLOAT_OOB_FILL_NONE);
}

// ----------------------------------------------------------------------------------
extern "C" void kernel_launch(void* const* d_in, const int* in_sizes, int n_in,
                              void* d_out, int out_size)
{
    const float* feats = (const float*)d_in[0];
    const float* w_kq  = (const float*)d_in[1];
    const float* b_kq  = (const float*)d_in[2];
    const float* w_v   = (const float*)d_in[3];
    const float* b_v   = (const float*)d_in[4];
    const float* w_out = (const float*)d_in[5];
    const float* b_out = (const float*)d_in[6];
    const float* w_bot = (const float*)d_in[7];
    const float* b_bot = (const float*)d_in[8];
    float* out = (float*)d_out;

    // driver encode fn (runtime-resolved; no -lcuda needed)
    PFN_encodeTiled encf = nullptr;
    {
        void* fp = nullptr;
        cudaDriverEntryPointQueryResult st;
        cudaGetDriverEntryPoint("cuTensorMapEncodeTiled", &fp, cudaEnableDefault, &st);
        encf = (PFN_encodeTiled)fp;
    }
    void *pA0h, *pA0l, *pA1h, *pA1l, *pFh, *pFl, *pCh, *pCl;
    cudaGetSymbolAddress(&pA0h, g_A0h);  cudaGetSymbolAddress(&pA0l, g_A0l);
    cudaGetSymbolAddress(&pA1h, g_A1h);  cudaGetSymbolAddress(&pA1l, g_A1l);
    cudaGetSymbolAddress(&pFh,  g_fh);   cudaGetSymbolAddress(&pFl,  g_fl);
    cudaGetSymbolAddress(&pCh,  g_ctxh); cudaGetSymbolAddress(&pCl,  g_ctxl);

    CUtensorMap mA0h, mA0l, mA1h, mA1l, mFh, mFl, mCh, mCl;
    enc2d(encf, &mA0h, pA0h, 512, 512, 64, 128);
    enc2d(encf, &mA0l, pA0l, 512, 512, 64, 128);
    enc2d(encf, &mA1h, pA1h, 512, 768, 64, 128);
    enc2d(encf, &mA1l, pA1l, 512, 768, 64, 128);
    enc2d(encf, &mFh,  pFh,  (unsigned long long)BATCH*512, HW, 64, 64);
    enc2d(encf, &mFl,  pFl,  (unsigned long long)BATCH*512, HW, 64, 64);
    enc2d(encf, &mCh,  pCh,  (unsigned long long)BATCH*256, HW, 64, 64);
    enc2d(encf, &mCl,  pCl,  (unsigned long long)BATCH*256, HW, 64, 64);

    const int pool_smem = 128*129*4;                 // 66048
    const int attn_smem = 157696 + 1024;             // 158720
    const int mma_smem  = 2*STAGE_B + 1024;          // 197632
    cudaFuncSetAttribute(pool_kernel, cudaFuncAttributeMaxDynamicSharedMemorySize, pool_smem);
    cudaFuncSetAttribute(attn_kernel, cudaFuncAttributeMaxDynamicSharedMemorySize, attn_smem);
    cudaFuncSetAttribute(mma_gemm_kernel<0>, cudaFuncAttributeMaxDynamicSharedMemorySize, mma_smem);
    cudaFuncSetAttribute(mma_gemm_kernel<1>, cudaFuncAttributeMaxDynamicSharedMemorySize, mma_smem);

    weff_kernel<<<512, 256>>>(w_out, b_out, w_bot, b_bot);
    splitA0_kernel<<<512, 256>>>(w_kq, w_v);
    splitA1_kernel<<<512, 256>>>(w_bot);
    split_feats_kernel<<<4096, 256>>>(feats);
    mma_gemm_kernel<0><<<dim3(4, 64, BATCH), 512, mma_smem>>>(
        mA0h, mA0l, mFh, mFl, mFh, mFl, b_kq, b_v, out);
    pool_kernel<<<dim3(2, 256, BATCH), 128, pool_smem>>>();
    attn_kernel<<<dim3(128, BATCH), 256, attn_smem>>>();
    mma_gemm_kernel<1><<<dim3(4, 64, BATCH), 512, mma_smem>>>(
        mA1h, mA1l, mCh, mCl, mFh, mFl, b_kq, b_v, out);
}